// round 1
// baseline (speedup 1.0000x reference)
#include <cuda_runtime.h>
#include <math.h>

#define EMBED 384
#define HEADS 6
#define HS    64
#define BATCH 64
#define SEQ   256
#define ROWS  (BATCH*SEQ)     // 16384
#define NQKV  (3*EMBED)       // 1152

// ------------------------- device scratch (no allocs allowed) ----------------
__device__ float g_ln  [ROWS*EMBED];   // 25.2 MB
__device__ float g_qkv [ROWS*NQKV];    // 75.5 MB
__device__ float g_attn[ROWS*EMBED];   // 25.2 MB
__device__ float g_ff  [ROWS*EMBED];   // 25.2 MB
__device__ float g_wqkv[EMBED*NQKV];   // 1.7 MB
__device__ float g_bqkv[NQKV];

// ------------------------- weight repack: [H,C,D]x3 -> [C, 3*H*D] ------------
__global__ void pack_qkv_kernel(const float* __restrict__ Wq,
                                const float* __restrict__ Wk,
                                const float* __restrict__ Wv,
                                const float* __restrict__ bq,
                                const float* __restrict__ bk,
                                const float* __restrict__ bv,
                                float* __restrict__ Wout,
                                float* __restrict__ bout) {
    int idx = blockIdx.x * 256 + threadIdx.x;
    if (idx < EMBED * NQKV) {
        int c   = idx / NQKV;
        int n   = idx % NQKV;
        int sel = n / EMBED;
        int hd  = n % EMBED;
        int h   = hd / HS;
        int d   = hd % HS;
        const float* W = (sel == 0) ? Wq : (sel == 1) ? Wk : Wv;
        Wout[idx] = W[((size_t)h * EMBED + c) * HS + d];
    }
    if (idx < NQKV) {
        int sel = idx / EMBED;
        int hd  = idx % EMBED;
        const float* bb = (sel == 0) ? bq : (sel == 1) ? bk : bv;
        bout[idx] = bb[hd];
    }
}

// ------------------------- LayerNorm: one row per block (384 threads) --------
__global__ void ln_kernel(const float* __restrict__ x,
                          const float* __restrict__ g,
                          const float* __restrict__ b,
                          float* __restrict__ out) {
    int row = blockIdx.x;
    int t   = threadIdx.x;   // 0..383
    float v = x[(size_t)row * EMBED + t];

    float s = v;
    #pragma unroll
    for (int o = 16; o; o >>= 1) s += __shfl_xor_sync(0xffffffffu, s, o);
    __shared__ float ws [12];
    __shared__ float ws2[12];
    if ((t & 31) == 0) ws[t >> 5] = s;
    __syncthreads();
    float tot = 0.f;
    #pragma unroll
    for (int i = 0; i < 12; i++) tot += ws[i];
    float mu = tot * (1.0f / EMBED);

    float d  = v - mu;
    float s2 = d * d;
    #pragma unroll
    for (int o = 16; o; o >>= 1) s2 += __shfl_xor_sync(0xffffffffu, s2, o);
    if ((t & 31) == 0) ws2[t >> 5] = s2;
    __syncthreads();
    float tot2 = 0.f;
    #pragma unroll
    for (int i = 0; i < 12; i++) tot2 += ws2[i];
    float var = tot2 * (1.0f / EMBED);

    out[(size_t)row * EMBED + t] = d * rsqrtf(var + 1e-5f) * g[t] + b[t];
}

// ------------------------- SGEMM: C[M,N] = A[M,K] @ B[K,N] (+bias,+relu,+res)
// 128x128 tile, K-tile 16, 256 threads, 8x8 per thread.
template<bool RELU>
__global__ __launch_bounds__(256)
void gemm128(const float* __restrict__ A, const float* __restrict__ Bm,
             const float* __restrict__ bias, const float* __restrict__ res,
             float* __restrict__ C, int N, int K) {
    __shared__ float As[16][128];
    __shared__ float Bs[16][128];
    const int tid = threadIdx.x;
    const int bm  = blockIdx.y * 128;
    const int bn  = blockIdx.x * 128;
    const int tx  = tid & 15;
    const int ty  = tid >> 4;

    float acc[8][8];
    #pragma unroll
    for (int i = 0; i < 8; i++)
        #pragma unroll
        for (int j = 0; j < 8; j++) acc[i][j] = 0.f;

    for (int k0 = 0; k0 < K; k0 += 16) {
        // A tile: 128 rows x 16 cols -> store transposed As[k][m]
        #pragma unroll
        for (int it = 0; it < 2; it++) {
            int li  = tid + it * 256;        // 0..511
            int row = li >> 2;
            int kq  = (li & 3) * 4;
            float4 v = *reinterpret_cast<const float4*>(
                &A[(size_t)(bm + row) * K + k0 + kq]);
            As[kq + 0][row] = v.x;
            As[kq + 1][row] = v.y;
            As[kq + 2][row] = v.z;
            As[kq + 3][row] = v.w;
        }
        // B tile: 16 rows x 128 cols, direct
        #pragma unroll
        for (int it = 0; it < 2; it++) {
            int li = tid + it * 256;
            int kr = li >> 5;
            int nq = (li & 31) * 4;
            *reinterpret_cast<float4*>(&Bs[kr][nq]) =
                *reinterpret_cast<const float4*>(
                    &Bm[(size_t)(k0 + kr) * N + bn + nq]);
        }
        __syncthreads();

        #pragma unroll
        for (int k = 0; k < 16; k++) {
            float a[8], b[8];
            *reinterpret_cast<float4*>(&a[0]) = *reinterpret_cast<float4*>(&As[k][ty * 8]);
            *reinterpret_cast<float4*>(&a[4]) = *reinterpret_cast<float4*>(&As[k][ty * 8 + 4]);
            *reinterpret_cast<float4*>(&b[0]) = *reinterpret_cast<float4*>(&Bs[k][tx * 8]);
            *reinterpret_cast<float4*>(&b[4]) = *reinterpret_cast<float4*>(&Bs[k][tx * 8 + 4]);
            #pragma unroll
            for (int i = 0; i < 8; i++)
                #pragma unroll
                for (int j = 0; j < 8; j++) acc[i][j] += a[i] * b[j];
        }
        __syncthreads();
    }

    #pragma unroll
    for (int i = 0; i < 8; i++) {
        int row = bm + ty * 8 + i;
        #pragma unroll
        for (int j = 0; j < 8; j++) {
            int col = bn + tx * 8 + j;
            float v = acc[i][j] + bias[col];
            if (RELU) v = fmaxf(v, 0.f);
            if (res)  v += res[(size_t)row * N + col];
            C[(size_t)row * N + col] = v;
        }
    }
}

// ------------------------- causal attention (flash-style) --------------------
// One block per (query-tile qt, head h, batch b). 256 threads.
// Q/K stored d-major transposed (width 68) so score loop is LDS.128-fed.
#define QT_W 68
#define PS_W 65
#define SM_ATTN_BYTES ((3*64*QT_W + 64*PS_W) * 4)

__global__ __launch_bounds__(256)
void attn_kernel(const float* __restrict__ qkv, float* __restrict__ out) {
    extern __shared__ float sm[];
    float* Qt = sm;                    // [64][68] indexed [d][r]
    float* Kt = sm + 64 * QT_W;        // [64][68] indexed [d][c]
    float* Vs = sm + 2 * 64 * QT_W;    // [64][68] indexed [s][d]
    float* Ps = sm + 3 * 64 * QT_W;    // [64][65] indexed [r][s]

    const int qt = blockIdx.x;   // 0..3
    const int h  = blockIdx.y;   // 0..5
    const int b  = blockIdx.z;   // 0..63
    const int tid = threadIdx.x;
    const int rg = tid >> 4;     // row group 0..15
    const int ci = tid & 15;     // col group 0..15
    const int r0 = rg * 4;
    const int c0 = ci * 4;
    const float scale = rsqrtf((float)EMBED);

    // Load Q tile (pre-scaled), transposed
    #pragma unroll
    for (int it = 0; it < 4; it++) {
        int li = tid + it * 256;         // 0..1023
        int r  = li >> 4;
        int d4 = (li & 15) * 4;
        float4 v = *reinterpret_cast<const float4*>(
            &qkv[(size_t)(b * SEQ + qt * 64 + r) * NQKV + h * HS + d4]);
        Qt[(d4 + 0) * QT_W + r] = v.x * scale;
        Qt[(d4 + 1) * QT_W + r] = v.y * scale;
        Qt[(d4 + 2) * QT_W + r] = v.z * scale;
        Qt[(d4 + 3) * QT_W + r] = v.w * scale;
    }

    float o[4][4];
    float m_i[4], l_i[4];
    #pragma unroll
    for (int i = 0; i < 4; i++) {
        m_i[i] = -1e30f; l_i[i] = 0.f;
        #pragma unroll
        for (int j = 0; j < 4; j++) o[i][j] = 0.f;
    }

    for (int st = 0; st <= qt; st++) {
        __syncthreads();   // protect Ks/Vs from previous iteration's readers
        // Load K (transposed) and V tiles
        #pragma unroll
        for (int it = 0; it < 4; it++) {
            int li = tid + it * 256;
            int r  = li >> 4;
            int d4 = (li & 15) * 4;
            const float* base =
                &qkv[(size_t)(b * SEQ + st * 64 + r) * NQKV + h * HS + d4];
            float4 kv = *reinterpret_cast<const float4*>(base + EMBED);
            Kt[(d4 + 0) * QT_W + r] = kv.x;
            Kt[(d4 + 1) * QT_W + r] = kv.y;
            Kt[(d4 + 2) * QT_W + r] = kv.z;
            Kt[(d4 + 3) * QT_W + r] = kv.w;
            float4 vv = *reinterpret_cast<const float4*>(base + 2 * EMBED);
            *reinterpret_cast<float4*>(&Vs[r * QT_W + d4]) = vv;
        }
        __syncthreads();

        // Scores: 4x4 block per thread
        float s_[4][4];
        #pragma unroll
        for (int i = 0; i < 4; i++)
            #pragma unroll
            for (int j = 0; j < 4; j++) s_[i][j] = 0.f;

        #pragma unroll 4
        for (int d = 0; d < 64; d++) {
            float4 qa = *reinterpret_cast<const float4*>(&Qt[d * QT_W + r0]);
            float4 kb = *reinterpret_cast<const float4*>(&Kt[d * QT_W + c0]);
            float qv[4] = {qa.x, qa.y, qa.z, qa.w};
            float kv[4] = {kb.x, kb.y, kb.z, kb.w};
            #pragma unroll
            for (int i = 0; i < 4; i++)
                #pragma unroll
                for (int j = 0; j < 4; j++) s_[i][j] += qv[i] * kv[j];
        }

        if (st == qt) {  // causal mask within diagonal tile (local idx compare)
            #pragma unroll
            for (int i = 0; i < 4; i++)
                #pragma unroll
                for (int j = 0; j < 4; j++)
                    if (c0 + j > r0 + i) s_[i][j] = -1e30f;
        }

        // Online softmax stats: the 16 threads sharing a row are contiguous lanes
        #pragma unroll
        for (int i = 0; i < 4; i++) {
            float mx = fmaxf(fmaxf(s_[i][0], s_[i][1]), fmaxf(s_[i][2], s_[i][3]));
            #pragma unroll
            for (int o2 = 8; o2; o2 >>= 1)
                mx = fmaxf(mx, __shfl_xor_sync(0xffffffffu, mx, o2));
            float m_new = fmaxf(m_i[i], mx);
            float alpha = __expf(m_i[i] - m_new);
            float rs = 0.f;
            #pragma unroll
            for (int j = 0; j < 4; j++) {
                float p = __expf(s_[i][j] - m_new);
                s_[i][j] = p;
                rs += p;
            }
            #pragma unroll
            for (int o2 = 8; o2; o2 >>= 1)
                rs += __shfl_xor_sync(0xffffffffu, rs, o2);
            l_i[i] = l_i[i] * alpha + rs;
            m_i[i] = m_new;
            #pragma unroll
            for (int j = 0; j < 4; j++) o[i][j] *= alpha;
        }

        // Stage P through smem so each thread can own O columns
        #pragma unroll
        for (int i = 0; i < 4; i++)
            #pragma unroll
            for (int j = 0; j < 4; j++)
                Ps[(r0 + i) * PS_W + c0 + j] = s_[i][j];
        __syncthreads();

        // O += P @ V ; thread owns rows r0..r0+3, cols d0..d0+3
        const int d0 = c0;
        #pragma unroll 4
        for (int s2 = 0; s2 < 64; s2++) {
            float4 vv = *reinterpret_cast<const float4*>(&Vs[s2 * QT_W + d0]);
            float vj[4] = {vv.x, vv.y, vv.z, vv.w};
            #pragma unroll
            for (int i = 0; i < 4; i++) {
                float p = Ps[(r0 + i) * PS_W + s2];
                #pragma unroll
                for (int j = 0; j < 4; j++) o[i][j] += p * vj[j];
            }
        }
    }

    // Normalize and write to [B,T,C] with c = h*64 + d
    #pragma unroll
    for (int i = 0; i < 4; i++) {
        float inv = 1.0f / l_i[i];
        float4 v;
        v.x = o[i][0] * inv; v.y = o[i][1] * inv;
        v.z = o[i][2] * inv; v.w = o[i][3] * inv;
        *reinterpret_cast<float4*>(
            &out[(size_t)(b * SEQ + qt * 64 + r0 + i) * EMBED + h * HS + c0]) = v;
    }
}

// ------------------------- launch ------------------------------------------
extern "C" void kernel_launch(void* const* d_in, const int* in_sizes, int n_in,
                              void* d_out, int out_size) {
    (void)in_sizes; (void)n_in; (void)out_size;
    const float* x     = (const float*)d_in[0];
    const float* Wq    = (const float*)d_in[1];
    const float* bq    = (const float*)d_in[2];
    const float* Wk    = (const float*)d_in[3];
    const float* bk    = (const float*)d_in[4];
    const float* Wv    = (const float*)d_in[5];
    const float* bv    = (const float*)d_in[6];
    const float* Wp    = (const float*)d_in[7];
    const float* bp    = (const float*)d_in[8];
    const float* W1    = (const float*)d_in[9];
    const float* b1    = (const float*)d_in[10];
    const float* W2    = (const float*)d_in[11];
    const float* b2    = (const float*)d_in[12];
    const float* ln1_g = (const float*)d_in[13];
    const float* ln1_b = (const float*)d_in[14];
    const float* ln2_g = (const float*)d_in[15];
    const float* ln2_b = (const float*)d_in[16];
    float* out = (float*)d_out;

    float *p_ln, *p_qkv, *p_attn, *p_ff, *p_wqkv, *p_bqkv;
    cudaGetSymbolAddress((void**)&p_ln,   g_ln);
    cudaGetSymbolAddress((void**)&p_qkv,  g_qkv);
    cudaGetSymbolAddress((void**)&p_attn, g_attn);
    cudaGetSymbolAddress((void**)&p_ff,   g_ff);
    cudaGetSymbolAddress((void**)&p_wqkv, g_wqkv);
    cudaGetSymbolAddress((void**)&p_bqkv, g_bqkv);

    cudaFuncSetAttribute(attn_kernel,
                         cudaFuncAttributeMaxDynamicSharedMemorySize,
                         SM_ATTN_BYTES);

    // 1. pack qkv weights -> [C, 3*H*D]
    pack_qkv_kernel<<<(EMBED * NQKV + 255) / 256, 256>>>(
        Wq, Wk, Wv, bq, bk, bv, p_wqkv, p_bqkv);

    // 2. LN1
    ln_kernel<<<ROWS, EMBED>>>(x, ln1_g, ln1_b, p_ln);

    // 3. QKV projection: [16384,384] @ [384,1152]
    {
        dim3 g(NQKV / 128, ROWS / 128);
        gemm128<false><<<g, 256>>>(p_ln, p_wqkv, p_bqkv, nullptr, p_qkv,
                                   NQKV, EMBED);
    }

    // 4. causal attention -> [B,T,C]
    attn_kernel<<<dim3(SEQ / 64, HEADS, BATCH), 256, SM_ATTN_BYTES>>>(
        p_qkv, p_attn);

    // 5. output projection + residual: out = x + attn @ Wp + bp
    {
        dim3 g(EMBED / 128, ROWS / 128);
        gemm128<false><<<g, 256>>>(p_attn, Wp, bp, x, out, EMBED, EMBED);
    }

    // 6. LN2
    ln_kernel<<<ROWS, EMBED>>>(out, ln2_g, ln2_b, p_ln);

    // 7. FFN layer 1 with relu
    {
        dim3 g(EMBED / 128, ROWS / 128);
        gemm128<true><<<g, 256>>>(p_ln, W1, b1, nullptr, p_ff, EMBED, EMBED);
    }

    // 8. FFN layer 2 + residual: out = out + ff @ W2 + b2
    {
        dim3 g(EMBED / 128, ROWS / 128);
        gemm128<false><<<g, 256>>>(p_ff, W2, b2, out, out, EMBED, EMBED);
    }
}

// round 5
// speedup vs baseline: 1.3190x; 1.3190x over previous
#include <cuda_runtime.h>
#include <math.h>
#include <stdint.h>

#define EMBED 384
#define HEADS 6
#define HS    64
#define BATCH 64
#define SEQ   256
#define ROWS  (BATCH*SEQ)     // 16384
#define NQKV  (3*EMBED)       // 1152

// ------------------------- device scratch (no allocs allowed) ----------------
__device__ float g_ln  [ROWS*EMBED];   // 25.2 MB
__device__ float g_qkv [ROWS*NQKV];    // 75.5 MB
__device__ float g_attn[ROWS*EMBED];   // 25.2 MB
__device__ float g_ff  [ROWS*EMBED];   // 25.2 MB
__device__ float g_wqkv[EMBED*NQKV];   // 1.7 MB
__device__ float g_bqkv[NQKV];

// ------------------------- weight repack: [H,C,D]x3 -> [C, 3*H*D] ------------
__global__ void pack_qkv_kernel(const float* __restrict__ Wq,
                                const float* __restrict__ Wk,
                                const float* __restrict__ Wv,
                                const float* __restrict__ bq,
                                const float* __restrict__ bk,
                                const float* __restrict__ bv,
                                float* __restrict__ Wout,
                                float* __restrict__ bout) {
    int idx = blockIdx.x * 256 + threadIdx.x;
    if (idx < EMBED * NQKV) {
        int c   = idx / NQKV;
        int n   = idx % NQKV;
        int sel = n / EMBED;
        int hd  = n % EMBED;
        int h   = hd / HS;
        int d   = hd % HS;
        const float* W = (sel == 0) ? Wq : (sel == 1) ? Wk : Wv;
        Wout[idx] = W[((size_t)h * EMBED + c) * HS + d];
    }
    if (idx < NQKV) {
        int sel = idx / EMBED;
        int hd  = idx % EMBED;
        const float* bb = (sel == 0) ? bq : (sel == 1) ? bk : bv;
        bout[idx] = bb[hd];
    }
}

// ------------------------- LayerNorm: one row per block (384 threads) --------
__global__ void ln_kernel(const float* __restrict__ x,
                          const float* __restrict__ g,
                          const float* __restrict__ b,
                          float* __restrict__ out) {
    int row = blockIdx.x;
    int t   = threadIdx.x;   // 0..383
    float v = x[(size_t)row * EMBED + t];

    float s = v;
    #pragma unroll
    for (int o = 16; o; o >>= 1) s += __shfl_xor_sync(0xffffffffu, s, o);
    __shared__ float ws [12];
    __shared__ float ws2[12];
    if ((t & 31) == 0) ws[t >> 5] = s;
    __syncthreads();
    float tot = 0.f;
    #pragma unroll
    for (int i = 0; i < 12; i++) tot += ws[i];
    float mu = tot * (1.0f / EMBED);

    float d  = v - mu;
    float s2 = d * d;
    #pragma unroll
    for (int o = 16; o; o >>= 1) s2 += __shfl_xor_sync(0xffffffffu, s2, o);
    if ((t & 31) == 0) ws2[t >> 5] = s2;
    __syncthreads();
    float tot2 = 0.f;
    #pragma unroll
    for (int i = 0; i < 12; i++) tot2 += ws2[i];
    float var = tot2 * (1.0f / EMBED);

    out[(size_t)row * EMBED + t] = d * rsqrtf(var + 1e-5f) * g[t] + b[t];
}

// ------------------------- TF32 tensor-core GEMM ----------------------------
// C[M,N] = A[M,K] @ B[K,N] (+bias, opt. relu, opt. residual)
// 128x128 CTA tile, k-tile 32, 256 threads (8 warps, 2x4), warp tile 64x32.
// mma.sync.m16n8k8 tf32, fp32 accumulate. Inputs rounded with cvt.rna.

__device__ __forceinline__ uint32_t f2tf32(float x) {
    uint32_t r;
    asm("cvt.rna.tf32.f32 %0, %1;" : "=r"(r) : "f"(x));
    return r;
}

__device__ __forceinline__ void mma_tf32(float d[4], const uint32_t a[4],
                                         const uint32_t b[2]) {
    asm volatile(
        "mma.sync.aligned.m16n8k8.row.col.f32.tf32.tf32.f32 "
        "{%0,%1,%2,%3}, {%4,%5,%6,%7}, {%8,%9}, {%0,%1,%2,%3};\n"
        : "+f"(d[0]), "+f"(d[1]), "+f"(d[2]), "+f"(d[3])
        : "r"(a[0]), "r"(a[1]), "r"(a[2]), "r"(a[3]), "r"(b[0]), "r"(b[1]));
}

#define A_PITCH 36    // A-frag read pattern: addr mod 32 = 4*gid + tig -> conflict-free
#define B_PITCH 136   // 128 cols + pad; 136 mod 32 = 8 -> addr mod 32 = 8*tig + gid -> conflict-free

template<bool RELU>
__global__ __launch_bounds__(256)
void gemm_tf32(const float* __restrict__ A, const float* __restrict__ Bm,
               const float* __restrict__ bias, const float* __restrict__ res,
               float* __restrict__ C, int N, int K) {
    __shared__ uint32_t As[128 * A_PITCH];   // [m][k]  18432 B
    __shared__ uint32_t Bs[32 * B_PITCH];    // [k][n]  17408 B

    const int tid  = threadIdx.x;
    const int bm   = blockIdx.y * 128;
    const int bn   = blockIdx.x * 128;
    const int warp = tid >> 5;
    const int lane = tid & 31;
    const int wm   = (warp >> 2) * 64;   // warp m-offset within CTA tile
    const int wn   = (warp & 3) * 32;    // warp n-offset
    const int gid  = lane >> 2;          // 0..7
    const int tig  = lane & 3;           // 0..3

    float acc[4][4][4];
    #pragma unroll
    for (int i = 0; i < 4; i++)
        #pragma unroll
        for (int j = 0; j < 4; j++)
            #pragma unroll
            for (int r = 0; r < 4; r++) acc[i][j][r] = 0.f;

    // global staging registers (one k-tile ahead)
    float4 aS[4], bS[4];
    const int a_r  = tid >> 3;          // 0..31 (+32*it)
    const int a_k4 = (tid & 7) * 4;
    const int b_k  = tid >> 5;          // 0..7 (+8*it)
    const int b_n4 = (tid & 31) * 4;

    auto ldg_tile = [&](int kt) {
        const int k0 = kt * 32;
        #pragma unroll
        for (int it = 0; it < 4; it++) {
            int r = a_r + it * 32;      // 0..127
            aS[it] = *reinterpret_cast<const float4*>(
                &A[(size_t)(bm + r) * K + k0 + a_k4]);
        }
        #pragma unroll
        for (int it = 0; it < 4; it++) {
            int kr = b_k + it * 8;      // 0..31
            bS[it] = *reinterpret_cast<const float4*>(
                &Bm[(size_t)(k0 + kr) * N + bn + b_n4]);
        }
    };

    const int NT = K / 32;
    ldg_tile(0);

    for (int kt = 0; kt < NT; kt++) {
        __syncthreads();   // previous k-tile's readers done
        // convert + store staged tile
        #pragma unroll
        for (int it = 0; it < 4; it++) {
            int r = a_r + it * 32;
            uint4 u;
            u.x = f2tf32(aS[it].x); u.y = f2tf32(aS[it].y);
            u.z = f2tf32(aS[it].z); u.w = f2tf32(aS[it].w);
            *reinterpret_cast<uint4*>(&As[r * A_PITCH + a_k4]) = u;
        }
        #pragma unroll
        for (int it = 0; it < 4; it++) {
            int kr = b_k + it * 8;
            uint4 u;
            u.x = f2tf32(bS[it].x); u.y = f2tf32(bS[it].y);
            u.z = f2tf32(bS[it].z); u.w = f2tf32(bS[it].w);
            *reinterpret_cast<uint4*>(&Bs[kr * B_PITCH + b_n4]) = u;
        }
        __syncthreads();

        if (kt + 1 < NT) ldg_tile(kt + 1);   // prefetch next tile

        #pragma unroll
        for (int ks = 0; ks < 4; ks++) {
            uint32_t af[4][4];
            #pragma unroll
            for (int mi = 0; mi < 4; mi++) {
                int row  = wm + mi * 16 + gid;
                int base = row * A_PITCH + ks * 8 + tig;
                af[mi][0] = As[base];
                af[mi][2] = As[base + 4];
                af[mi][1] = As[base + 8 * A_PITCH];
                af[mi][3] = As[base + 8 * A_PITCH + 4];
            }
            uint32_t bf[4][2];
            #pragma unroll
            for (int nj = 0; nj < 4; nj++) {
                int col = wn + nj * 8 + gid;
                bf[nj][0] = Bs[(ks * 8 + tig)     * B_PITCH + col];
                bf[nj][1] = Bs[(ks * 8 + tig + 4) * B_PITCH + col];
            }
            #pragma unroll
            for (int mi = 0; mi < 4; mi++)
                #pragma unroll
                for (int nj = 0; nj < 4; nj++)
                    mma_tf32(acc[mi][nj], af[mi], bf[nj]);
        }
    }

    // epilogue
    #pragma unroll
    for (int mi = 0; mi < 4; mi++) {
        int row = bm + wm + mi * 16 + gid;
        #pragma unroll
        for (int nj = 0; nj < 4; nj++) {
            int col = bn + wn + nj * 8 + tig * 2;
            float2 bv = *reinterpret_cast<const float2*>(&bias[col]);
            float v0 = acc[mi][nj][0] + bv.x;
            float v1 = acc[mi][nj][1] + bv.y;
            float v2 = acc[mi][nj][2] + bv.x;
            float v3 = acc[mi][nj][3] + bv.y;
            if (RELU) {
                v0 = fmaxf(v0, 0.f); v1 = fmaxf(v1, 0.f);
                v2 = fmaxf(v2, 0.f); v3 = fmaxf(v3, 0.f);
            }
            if (res) {
                float2 r0 = *reinterpret_cast<const float2*>(
                    &res[(size_t)row * N + col]);
                float2 r1 = *reinterpret_cast<const float2*>(
                    &res[(size_t)(row + 8) * N + col]);
                v0 += r0.x; v1 += r0.y; v2 += r1.x; v3 += r1.y;
            }
            *reinterpret_cast<float2*>(&C[(size_t)row * N + col]) =
                make_float2(v0, v1);
            *reinterpret_cast<float2*>(&C[(size_t)(row + 8) * N + col]) =
                make_float2(v2, v3);
        }
    }
}

// ------------------------- causal attention (flash-style) --------------------
// One block per (query-tile qt, head h, batch b). 256 threads.
#define QT_W 68
#define PS_W 65
#define SM_ATTN_BYTES ((3*64*QT_W + 64*PS_W) * 4)

__global__ __launch_bounds__(256)
void attn_kernel(const float* __restrict__ qkv, float* __restrict__ out) {
    extern __shared__ float sm[];
    float* Qt = sm;                    // [64][68] indexed [d][r]
    float* Kt = sm + 64 * QT_W;        // [64][68] indexed [d][c]
    float* Vs = sm + 2 * 64 * QT_W;    // [64][68] indexed [s][d]
    float* Ps = sm + 3 * 64 * QT_W;    // [64][65] indexed [r][s]

    const int qt = blockIdx.x;   // 0..3
    const int h  = blockIdx.y;   // 0..5
    const int b  = blockIdx.z;   // 0..63
    const int tid = threadIdx.x;
    const int rg = tid >> 4;     // row group 0..15
    const int ci = tid & 15;     // col group 0..15
    const int r0 = rg * 4;
    const int c0 = ci * 4;
    const float scale = rsqrtf((float)EMBED);

    #pragma unroll
    for (int it = 0; it < 4; it++) {
        int li = tid + it * 256;
        int r  = li >> 4;
        int d4 = (li & 15) * 4;
        float4 v = *reinterpret_cast<const float4*>(
            &qkv[(size_t)(b * SEQ + qt * 64 + r) * NQKV + h * HS + d4]);
        Qt[(d4 + 0) * QT_W + r] = v.x * scale;
        Qt[(d4 + 1) * QT_W + r] = v.y * scale;
        Qt[(d4 + 2) * QT_W + r] = v.z * scale;
        Qt[(d4 + 3) * QT_W + r] = v.w * scale;
    }

    float o[4][4];
    float m_i[4], l_i[4];
    #pragma unroll
    for (int i = 0; i < 4; i++) {
        m_i[i] = -1e30f; l_i[i] = 0.f;
        #pragma unroll
        for (int j = 0; j < 4; j++) o[i][j] = 0.f;
    }

    for (int st = 0; st <= qt; st++) {
        __syncthreads();
        #pragma unroll
        for (int it = 0; it < 4; it++) {
            int li = tid + it * 256;
            int r  = li >> 4;
            int d4 = (li & 15) * 4;
            const float* base =
                &qkv[(size_t)(b * SEQ + st * 64 + r) * NQKV + h * HS + d4];
            float4 kv = *reinterpret_cast<const float4*>(base + EMBED);
            Kt[(d4 + 0) * QT_W + r] = kv.x;
            Kt[(d4 + 1) * QT_W + r] = kv.y;
            Kt[(d4 + 2) * QT_W + r] = kv.z;
            Kt[(d4 + 3) * QT_W + r] = kv.w;
            float4 vv = *reinterpret_cast<const float4*>(base + 2 * EMBED);
            *reinterpret_cast<float4*>(&Vs[r * QT_W + d4]) = vv;
        }
        __syncthreads();

        float s_[4][4];
        #pragma unroll
        for (int i = 0; i < 4; i++)
            #pragma unroll
            for (int j = 0; j < 4; j++) s_[i][j] = 0.f;

        #pragma unroll 4
        for (int d = 0; d < 64; d++) {
            float4 qa = *reinterpret_cast<const float4*>(&Qt[d * QT_W + r0]);
            float4 kb = *reinterpret_cast<const float4*>(&Kt[d * QT_W + c0]);
            float qv[4] = {qa.x, qa.y, qa.z, qa.w};
            float kv[4] = {kb.x, kb.y, kb.z, kb.w};
            #pragma unroll
            for (int i = 0; i < 4; i++)
                #pragma unroll
                for (int j = 0; j < 4; j++) s_[i][j] += qv[i] * kv[j];
        }

        if (st == qt) {
            #pragma unroll
            for (int i = 0; i < 4; i++)
                #pragma unroll
                for (int j = 0; j < 4; j++)
                    if (c0 + j > r0 + i) s_[i][j] = -1e30f;
        }

        #pragma unroll
        for (int i = 0; i < 4; i++) {
            float mx = fmaxf(fmaxf(s_[i][0], s_[i][1]), fmaxf(s_[i][2], s_[i][3]));
            #pragma unroll
            for (int o2 = 8; o2; o2 >>= 1)
                mx = fmaxf(mx, __shfl_xor_sync(0xffffffffu, mx, o2));
            float m_new = fmaxf(m_i[i], mx);
            float alpha = __expf(m_i[i] - m_new);
            float rs = 0.f;
            #pragma unroll
            for (int j = 0; j < 4; j++) {
                float p = __expf(s_[i][j] - m_new);
                s_[i][j] = p;
                rs += p;
            }
            #pragma unroll
            for (int o2 = 8; o2; o2 >>= 1)
                rs += __shfl_xor_sync(0xffffffffu, rs, o2);
            l_i[i] = l_i[i] * alpha + rs;
            m_i[i] = m_new;
            #pragma unroll
            for (int j = 0; j < 4; j++) o[i][j] *= alpha;
        }

        #pragma unroll
        for (int i = 0; i < 4; i++)
            #pragma unroll
            for (int j = 0; j < 4; j++)
                Ps[(r0 + i) * PS_W + c0 + j] = s_[i][j];
        __syncthreads();

        const int d0 = c0;
        #pragma unroll 4
        for (int s2 = 0; s2 < 64; s2++) {
            float4 vv = *reinterpret_cast<const float4*>(&Vs[s2 * QT_W + d0]);
            float vj[4] = {vv.x, vv.y, vv.z, vv.w};
            #pragma unroll
            for (int i = 0; i < 4; i++) {
                float p = Ps[(r0 + i) * PS_W + s2];
                #pragma unroll
                for (int j = 0; j < 4; j++) o[i][j] += p * vj[j];
            }
        }
    }

    #pragma unroll
    for (int i = 0; i < 4; i++) {
        float inv = 1.0f / l_i[i];
        float4 v;
        v.x = o[i][0] * inv; v.y = o[i][1] * inv;
        v.z = o[i][2] * inv; v.w = o[i][3] * inv;
        *reinterpret_cast<float4*>(
            &out[(size_t)(b * SEQ + qt * 64 + r0 + i) * EMBED + h * HS + c0]) = v;
    }
}

// ------------------------- launch ------------------------------------------
extern "C" void kernel_launch(void* const* d_in, const int* in_sizes, int n_in,
                              void* d_out, int out_size) {
    (void)in_sizes; (void)n_in; (void)out_size;
    const float* x     = (const float*)d_in[0];
    const float* Wq    = (const float*)d_in[1];
    const float* bq    = (const float*)d_in[2];
    const float* Wk    = (const float*)d_in[3];
    const float* bk    = (const float*)d_in[4];
    const float* Wv    = (const float*)d_in[5];
    const float* bv    = (const float*)d_in[6];
    const float* Wp    = (const float*)d_in[7];
    const float* bp    = (const float*)d_in[8];
    const float* W1    = (const float*)d_in[9];
    const float* b1    = (const float*)d_in[10];
    const float* W2    = (const float*)d_in[11];
    const float* b2    = (const float*)d_in[12];
    const float* ln1_g = (const float*)d_in[13];
    const float* ln1_b = (const float*)d_in[14];
    const float* ln2_g = (const float*)d_in[15];
    const float* ln2_b = (const float*)d_in[16];
    float* out = (float*)d_out;

    float *p_ln, *p_qkv, *p_attn, *p_ff, *p_wqkv, *p_bqkv;
    cudaGetSymbolAddress((void**)&p_ln,   g_ln);
    cudaGetSymbolAddress((void**)&p_qkv,  g_qkv);
    cudaGetSymbolAddress((void**)&p_attn, g_attn);
    cudaGetSymbolAddress((void**)&p_ff,   g_ff);
    cudaGetSymbolAddress((void**)&p_wqkv, g_wqkv);
    cudaGetSymbolAddress((void**)&p_bqkv, g_bqkv);

    cudaFuncSetAttribute(attn_kernel,
                         cudaFuncAttributeMaxDynamicSharedMemorySize,
                         SM_ATTN_BYTES);

    // 1. pack qkv weights -> [C, 3*H*D]
    pack_qkv_kernel<<<(EMBED * NQKV + 255) / 256, 256>>>(
        Wq, Wk, Wv, bq, bk, bv, p_wqkv, p_bqkv);

    // 2. LN1
    ln_kernel<<<ROWS, EMBED>>>(x, ln1_g, ln1_b, p_ln);

    // 3. QKV projection: [16384,384] @ [384,1152]   (tf32 tensor cores)
    {
        dim3 g(NQKV / 128, ROWS / 128);
        gemm_tf32<false><<<g, 256>>>(p_ln, p_wqkv, p_bqkv, nullptr, p_qkv,
                                     NQKV, EMBED);
    }

    // 4. causal attention -> [B,T,C]
    attn_kernel<<<dim3(SEQ / 64, HEADS, BATCH), 256, SM_ATTN_BYTES>>>(
        p_qkv, p_attn);

    // 5. output projection + residual: out = x + attn @ Wp + bp
    {
        dim3 g(EMBED / 128, ROWS / 128);
        gemm_tf32<false><<<g, 256>>>(p_attn, Wp, bp, x, out, EMBED, EMBED);
    }

    // 6. LN2
    ln_kernel<<<ROWS, EMBED>>>(out, ln2_g, ln2_b, p_ln);

    // 7. FFN layer 1 with relu
    {
        dim3 g(EMBED / 128, ROWS / 128);
        gemm_tf32<true><<<g, 256>>>(p_ln, W1, b1, nullptr, p_ff, EMBED, EMBED);
    }

    // 8. FFN layer 2 + residual: out = out + ff @ W2 + b2
    {
        dim3 g(EMBED / 128, ROWS / 128);
        gemm_tf32<false><<<g, 256>>>(p_ff, W2, b2, out, out, EMBED, EMBED);
    }
}

// round 7
// speedup vs baseline: 2.4727x; 1.8746x over previous
#include <cuda_runtime.h>
#include <math.h>
#include <stdint.h>

#define EMBED 384
#define HEADS 6
#define HS    64
#define BATCH 64
#define SEQ   256
#define ROWS  (BATCH*SEQ)     // 16384
#define NQKV  (3*EMBED)       // 1152

// ------------------------- device scratch (no allocs allowed) ----------------
__device__ float g_ln  [ROWS*EMBED];
__device__ float g_qkv [ROWS*NQKV];
__device__ float g_attn[ROWS*EMBED];
__device__ float g_ff  [ROWS*EMBED];
__device__ float g_wqkv[EMBED*NQKV];
__device__ float g_bqkv[NQKV];

// ------------------------- weight repack: [H,C,D]x3 -> [C, 3*H*D] ------------
__global__ void pack_qkv_kernel(const float* __restrict__ Wq,
                                const float* __restrict__ Wk,
                                const float* __restrict__ Wv,
                                const float* __restrict__ bq,
                                const float* __restrict__ bk,
                                const float* __restrict__ bv,
                                float* __restrict__ Wout,
                                float* __restrict__ bout) {
    int idx = blockIdx.x * 256 + threadIdx.x;
    if (idx < EMBED * NQKV) {
        int c   = idx / NQKV;
        int n   = idx % NQKV;
        int sel = n / EMBED;
        int hd  = n % EMBED;
        int h   = hd / HS;
        int d   = hd % HS;
        const float* W = (sel == 0) ? Wq : (sel == 1) ? Wk : Wv;
        Wout[idx] = W[((size_t)h * EMBED + c) * HS + d];
    }
    if (idx < NQKV) {
        int sel = idx / EMBED;
        int hd  = idx % EMBED;
        const float* bb = (sel == 0) ? bq : (sel == 1) ? bk : bv;
        bout[idx] = bb[hd];
    }
}

// ------------------------- LayerNorm ----------------------------------------
__global__ void ln_kernel(const float* __restrict__ x,
                          const float* __restrict__ g,
                          const float* __restrict__ b,
                          float* __restrict__ out) {
    int row = blockIdx.x;
    int t   = threadIdx.x;   // 0..383
    float v = x[(size_t)row * EMBED + t];

    float s = v;
    #pragma unroll
    for (int o = 16; o; o >>= 1) s += __shfl_xor_sync(0xffffffffu, s, o);
    __shared__ float ws [12];
    __shared__ float ws2[12];
    if ((t & 31) == 0) ws[t >> 5] = s;
    __syncthreads();
    float tot = 0.f;
    #pragma unroll
    for (int i = 0; i < 12; i++) tot += ws[i];
    float mu = tot * (1.0f / EMBED);

    float d  = v - mu;
    float s2 = d * d;
    #pragma unroll
    for (int o = 16; o; o >>= 1) s2 += __shfl_xor_sync(0xffffffffu, s2, o);
    if ((t & 31) == 0) ws2[t >> 5] = s2;
    __syncthreads();
    float tot2 = 0.f;
    #pragma unroll
    for (int i = 0; i < 12; i++) tot2 += ws2[i];
    float var = tot2 * (1.0f / EMBED);

    out[(size_t)row * EMBED + t] = d * rsqrtf(var + 1e-5f) * g[t] + b[t];
}

// ------------------------- tf32 helpers -------------------------------------
__device__ __forceinline__ uint32_t f2tf32(float x) {
    uint32_t r;
    asm("cvt.rna.tf32.f32 %0, %1;" : "=r"(r) : "f"(x));
    return r;
}

__device__ __forceinline__ void mma_tf32(float d[4], const uint32_t a[4],
                                         const uint32_t b[2]) {
    asm volatile(
        "mma.sync.aligned.m16n8k8.row.col.f32.tf32.tf32.f32 "
        "{%0,%1,%2,%3}, {%4,%5,%6,%7}, {%8,%9}, {%0,%1,%2,%3};\n"
        : "+f"(d[0]), "+f"(d[1]), "+f"(d[2]), "+f"(d[3])
        : "r"(a[0]), "r"(a[1]), "r"(a[2]), "r"(a[3]), "r"(b[0]), "r"(b[1]));
}

// ------------------------- TF32 tensor-core GEMM ----------------------------
#define A_PITCH 36
#define B_PITCH 136

template<bool RELU>
__global__ __launch_bounds__(256)
void gemm_tf32(const float* __restrict__ A, const float* __restrict__ Bm,
               const float* __restrict__ bias, const float* __restrict__ res,
               float* __restrict__ C, int N, int K) {
    __shared__ uint32_t As[128 * A_PITCH];
    __shared__ uint32_t Bs[32 * B_PITCH];

    const int tid  = threadIdx.x;
    const int bm   = blockIdx.y * 128;
    const int bn   = blockIdx.x * 128;
    const int warp = tid >> 5;
    const int lane = tid & 31;
    const int wm   = (warp >> 2) * 64;
    const int wn   = (warp & 3) * 32;
    const int gid  = lane >> 2;
    const int tig  = lane & 3;

    float acc[4][4][4];
    #pragma unroll
    for (int i = 0; i < 4; i++)
        #pragma unroll
        for (int j = 0; j < 4; j++)
            #pragma unroll
            for (int r = 0; r < 4; r++) acc[i][j][r] = 0.f;

    float4 aS[4], bS[4];
    const int a_r  = tid >> 3;
    const int a_k4 = (tid & 7) * 4;
    const int b_k  = tid >> 5;
    const int b_n4 = (tid & 31) * 4;

    auto ldg_tile = [&](int kt) {
        const int k0 = kt * 32;
        #pragma unroll
        for (int it = 0; it < 4; it++) {
            int r = a_r + it * 32;
            aS[it] = *reinterpret_cast<const float4*>(
                &A[(size_t)(bm + r) * K + k0 + a_k4]);
        }
        #pragma unroll
        for (int it = 0; it < 4; it++) {
            int kr = b_k + it * 8;
            bS[it] = *reinterpret_cast<const float4*>(
                &Bm[(size_t)(k0 + kr) * N + bn + b_n4]);
        }
    };

    const int NT = K / 32;
    ldg_tile(0);

    for (int kt = 0; kt < NT; kt++) {
        __syncthreads();
        #pragma unroll
        for (int it = 0; it < 4; it++) {
            int r = a_r + it * 32;
            uint4 u;
            u.x = f2tf32(aS[it].x); u.y = f2tf32(aS[it].y);
            u.z = f2tf32(aS[it].z); u.w = f2tf32(aS[it].w);
            *reinterpret_cast<uint4*>(&As[r * A_PITCH + a_k4]) = u;
        }
        #pragma unroll
        for (int it = 0; it < 4; it++) {
            int kr = b_k + it * 8;
            uint4 u;
            u.x = f2tf32(bS[it].x); u.y = f2tf32(bS[it].y);
            u.z = f2tf32(bS[it].z); u.w = f2tf32(bS[it].w);
            *reinterpret_cast<uint4*>(&Bs[kr * B_PITCH + b_n4]) = u;
        }
        __syncthreads();

        if (kt + 1 < NT) ldg_tile(kt + 1);

        #pragma unroll
        for (int ks = 0; ks < 4; ks++) {
            uint32_t af[4][4];
            #pragma unroll
            for (int mi = 0; mi < 4; mi++) {
                int row  = wm + mi * 16 + gid;
                int base = row * A_PITCH + ks * 8 + tig;
                af[mi][0] = As[base];
                af[mi][2] = As[base + 4];
                af[mi][1] = As[base + 8 * A_PITCH];
                af[mi][3] = As[base + 8 * A_PITCH + 4];
            }
            uint32_t bf[4][2];
            #pragma unroll
            for (int nj = 0; nj < 4; nj++) {
                int col = wn + nj * 8 + gid;
                bf[nj][0] = Bs[(ks * 8 + tig)     * B_PITCH + col];
                bf[nj][1] = Bs[(ks * 8 + tig + 4) * B_PITCH + col];
            }
            #pragma unroll
            for (int mi = 0; mi < 4; mi++)
                #pragma unroll
                for (int nj = 0; nj < 4; nj++)
                    mma_tf32(acc[mi][nj], af[mi], bf[nj]);
        }
    }

    #pragma unroll
    for (int mi = 0; mi < 4; mi++) {
        int row = bm + wm + mi * 16 + gid;
        #pragma unroll
        for (int nj = 0; nj < 4; nj++) {
            int col = bn + wn + nj * 8 + tig * 2;
            float2 bv = *reinterpret_cast<const float2*>(&bias[col]);
            float v0 = acc[mi][nj][0] + bv.x;
            float v1 = acc[mi][nj][1] + bv.y;
            float v2 = acc[mi][nj][2] + bv.x;
            float v3 = acc[mi][nj][3] + bv.y;
            if (RELU) {
                v0 = fmaxf(v0, 0.f); v1 = fmaxf(v1, 0.f);
                v2 = fmaxf(v2, 0.f); v3 = fmaxf(v3, 0.f);
            }
            if (res) {
                float2 r0 = *reinterpret_cast<const float2*>(
                    &res[(size_t)row * N + col]);
                float2 r1 = *reinterpret_cast<const float2*>(
                    &res[(size_t)(row + 8) * N + col]);
                v0 += r0.x; v1 += r0.y; v2 += r1.x; v3 += r1.y;
            }
            *reinterpret_cast<float2*>(&C[(size_t)row * N + col]) =
                make_float2(v0, v1);
            *reinterpret_cast<float2*>(&C[(size_t)(row + 8) * N + col]) =
                make_float2(v2, v3);
        }
    }
}

// ------------------------- tensor-core flash attention ----------------------
// CTA: 128 q-rows of one (b,h). 8 warps, warp owns 16 rows (warp-local softmax).
// K-tile = 64 keys/iter. mma.m16n8k8 tf32. exp2-based softmax (log2e folded
// into Q scale). Smem: Q[128][68] + K[64][68] + Vt[64][68] (tf32 bits).
#define QP 68
#define SM_ATTN_BYTES ((128*QP + 64*QP + 64*QP) * 4)   // 69632

__global__ __launch_bounds__(256)
void attn_tc_kernel(const float* __restrict__ qkv, float* __restrict__ out) {
    extern __shared__ uint32_t sh[];
    uint32_t* Qs = sh;                       // [128][QP]  row r, col d
    uint32_t* Ks = sh + 128 * QP;            // [64][QP]   row c, col d
    uint32_t* Vt = sh + (128 + 64) * QP;     // [64][QP]   row d, col s

    const int qt  = 1 - blockIdx.x;          // heavy tile first
    const int h   = blockIdx.y;
    const int b   = blockIdx.z;
    const int q0  = qt * 128;
    const int tid  = threadIdx.x;
    const int warp = tid >> 5;
    const int lane = tid & 31;
    const int gid  = lane >> 2;              // 0..7
    const int tig  = lane & 3;               // 0..3
    const int wr0  = warp * 16;
    const float qscale = rsqrtf((float)EMBED) * 1.4426950408889634f; // /sqrt(C) * log2(e)

    // ---- load Q tile (tf32, pre-scaled) ----
    #pragma unroll
    for (int it = 0; it < 8; it++) {
        int li = tid + it * 256;             // 0..2047
        int r  = li >> 4;
        int d4 = (li & 15) * 4;
        float4 v = *reinterpret_cast<const float4*>(
            &qkv[(size_t)(b * SEQ + q0 + r) * NQKV + h * HS + d4]);
        uint4 u;
        u.x = f2tf32(v.x * qscale); u.y = f2tf32(v.y * qscale);
        u.z = f2tf32(v.z * qscale); u.w = f2tf32(v.w * qscale);
        *reinterpret_cast<uint4*>(&Qs[r * QP + d4]) = u;
    }

    float oacc[8][4];
    #pragma unroll
    for (int i = 0; i < 8; i++)
        #pragma unroll
        for (int j = 0; j < 4; j++) oacc[i][j] = 0.f;
    float m0 = -1e30f, m1 = -1e30f, l0 = 0.f, l1 = 0.f;

    const int nst = q0 / 64 + 2;             // qt0:2, qt1:4

    for (int st = 0; st < nst; st++) {
        __syncthreads();                     // Q visible / prev iter readers done
        // ---- load K tile [c][d] ----
        #pragma unroll
        for (int it = 0; it < 4; it++) {
            int li = tid + it * 256;         // 0..1023
            int r  = li >> 4;
            int d4 = (li & 15) * 4;
            float4 kv = *reinterpret_cast<const float4*>(
                &qkv[(size_t)(b * SEQ + st * 64 + r) * NQKV + EMBED + h * HS + d4]);
            uint4 u;
            u.x = f2tf32(kv.x); u.y = f2tf32(kv.y);
            u.z = f2tf32(kv.z); u.w = f2tf32(kv.w);
            *reinterpret_cast<uint4*>(&Ks[r * QP + d4]) = u;
        }
        // ---- load V tile transposed [d][s] (s = lane -> conflict-free STS) ----
        #pragma unroll
        for (int it = 0; it < 4; it++) {
            int li = tid + it * 256;
            int s  = li & 63;
            int d4 = (li >> 6) * 4;
            float4 vv = *reinterpret_cast<const float4*>(
                &qkv[(size_t)(b * SEQ + st * 64 + s) * NQKV + 2 * EMBED + h * HS + d4]);
            Vt[(d4 + 0) * QP + s] = f2tf32(vv.x);
            Vt[(d4 + 1) * QP + s] = f2tf32(vv.y);
            Vt[(d4 + 2) * QP + s] = f2tf32(vv.z);
            Vt[(d4 + 3) * QP + s] = f2tf32(vv.w);
        }
        __syncthreads();

        // ---- S = Q K^T  (16 rows x 64 cols per warp) ----
        float sacc[8][4];
        #pragma unroll
        for (int i = 0; i < 8; i++)
            #pragma unroll
            for (int j = 0; j < 4; j++) sacc[i][j] = 0.f;

        #pragma unroll
        for (int ks = 0; ks < 8; ks++) {
            uint32_t qa[4];
            int qb = (wr0 + gid) * QP + ks * 8 + tig;
            qa[0] = Qs[qb];
            qa[1] = Qs[qb + 8 * QP];
            qa[2] = Qs[qb + 4];
            qa[3] = Qs[qb + 8 * QP + 4];
            #pragma unroll
            for (int nt = 0; nt < 8; nt++) {
                uint32_t bk[2];
                int kb = (nt * 8 + gid) * QP + ks * 8 + tig;
                bk[0] = Ks[kb];
                bk[1] = Ks[kb + 4];
                mma_tf32(sacc[nt], qa, bk);
            }
        }

        // ---- causal mask (only tiles overlapping the diagonal) ----
        const int r0g = q0 + wr0 + gid;
        const int r1g = r0g + 8;
        if (st * 64 + 63 > r0g - gid) {      // st*64+63 > q0+wr0
            #pragma unroll
            for (int nt = 0; nt < 8; nt++) {
                int cb = st * 64 + nt * 8 + 2 * tig;
                if (cb     > r0g) sacc[nt][0] = -1e30f;
                if (cb + 1 > r0g) sacc[nt][1] = -1e30f;
                if (cb     > r1g) sacc[nt][2] = -1e30f;
                if (cb + 1 > r1g) sacc[nt][3] = -1e30f;
            }
        }

        // ---- online softmax (base-2), row stats via quad shuffles ----
        float mx0 = -1e30f, mx1 = -1e30f;
        #pragma unroll
        for (int nt = 0; nt < 8; nt++) {
            mx0 = fmaxf(mx0, fmaxf(sacc[nt][0], sacc[nt][1]));
            mx1 = fmaxf(mx1, fmaxf(sacc[nt][2], sacc[nt][3]));
        }
        #pragma unroll
        for (int o = 1; o <= 2; o <<= 1) {
            mx0 = fmaxf(mx0, __shfl_xor_sync(0xffffffffu, mx0, o));
            mx1 = fmaxf(mx1, __shfl_xor_sync(0xffffffffu, mx1, o));
        }
        float mn0 = fmaxf(m0, mx0), mn1 = fmaxf(m1, mx1);
        float al0 = exp2f(m0 - mn0), al1 = exp2f(m1 - mn1);
        m0 = mn0; m1 = mn1;

        float ls0 = 0.f, ls1 = 0.f;
        #pragma unroll
        for (int nt = 0; nt < 8; nt++) {
            float p0 = exp2f(sacc[nt][0] - mn0);
            float p1 = exp2f(sacc[nt][1] - mn0);
            float p2 = exp2f(sacc[nt][2] - mn1);
            float p3 = exp2f(sacc[nt][3] - mn1);
            sacc[nt][0] = p0; sacc[nt][1] = p1;
            sacc[nt][2] = p2; sacc[nt][3] = p3;
            ls0 += p0 + p1; ls1 += p2 + p3;
        }
        l0 = l0 * al0 + ls0;
        l1 = l1 * al1 + ls1;
        #pragma unroll
        for (int dn = 0; dn < 8; dn++) {
            oacc[dn][0] *= al0; oacc[dn][1] *= al0;
            oacc[dn][2] *= al1; oacc[dn][3] *= al1;
        }

        // ---- O += P @ V : rearrange P (c-layout -> a-frag) via quad shuffles
        const int s0l = 4 * gid + (tig >> 1);
        const bool odd = tig & 1;
        #pragma unroll
        for (int kc = 0; kc < 8; kc++) {
            float v00 = __shfl_sync(0xffffffffu, sacc[kc][0], s0l);
            float v01 = __shfl_sync(0xffffffffu, sacc[kc][1], s0l);
            float v10 = __shfl_sync(0xffffffffu, sacc[kc][2], s0l);
            float v11 = __shfl_sync(0xffffffffu, sacc[kc][3], s0l);
            float v20 = __shfl_sync(0xffffffffu, sacc[kc][0], s0l + 2);
            float v21 = __shfl_sync(0xffffffffu, sacc[kc][1], s0l + 2);
            float v30 = __shfl_sync(0xffffffffu, sacc[kc][2], s0l + 2);
            float v31 = __shfl_sync(0xffffffffu, sacc[kc][3], s0l + 2);
            uint32_t pa[4];
            pa[0] = f2tf32(odd ? v01 : v00);
            pa[1] = f2tf32(odd ? v11 : v10);
            pa[2] = f2tf32(odd ? v21 : v20);
            pa[3] = f2tf32(odd ? v31 : v30);
            #pragma unroll
            for (int dn = 0; dn < 8; dn++) {
                uint32_t bv[2];
                int vb = (dn * 8 + gid) * QP + kc * 8 + tig;
                bv[0] = Vt[vb];
                bv[1] = Vt[vb + 4];
                mma_tf32(oacc[dn], pa, bv);
            }
        }
    }

    // ---- finalize: row-sum l across quad, normalize, store ----
    #pragma unroll
    for (int o = 1; o <= 2; o <<= 1) {
        l0 += __shfl_xor_sync(0xffffffffu, l0, o);
        l1 += __shfl_xor_sync(0xffffffffu, l1, o);
    }
    float inv0 = 1.f / l0, inv1 = 1.f / l1;
    const int row0 = b * SEQ + q0 + wr0 + gid;
    #pragma unroll
    for (int dn = 0; dn < 8; dn++) {
        int col = h * HS + dn * 8 + 2 * tig;
        *reinterpret_cast<float2*>(&out[(size_t)row0 * EMBED + col]) =
            make_float2(oacc[dn][0] * inv0, oacc[dn][1] * inv0);
        *reinterpret_cast<float2*>(&out[(size_t)(row0 + 8) * EMBED + col]) =
            make_float2(oacc[dn][2] * inv1, oacc[dn][3] * inv1);
    }
}

// ------------------------- launch ------------------------------------------
extern "C" void kernel_launch(void* const* d_in, const int* in_sizes, int n_in,
                              void* d_out, int out_size) {
    (void)in_sizes; (void)n_in; (void)out_size;
    const float* x     = (const float*)d_in[0];
    const float* Wq    = (const float*)d_in[1];
    const float* bq    = (const float*)d_in[2];
    const float* Wk    = (const float*)d_in[3];
    const float* bk    = (const float*)d_in[4];
    const float* Wv    = (const float*)d_in[5];
    const float* bv    = (const float*)d_in[6];
    const float* Wp    = (const float*)d_in[7];
    const float* bp    = (const float*)d_in[8];
    const float* W1    = (const float*)d_in[9];
    const float* b1    = (const float*)d_in[10];
    const float* W2    = (const float*)d_in[11];
    const float* b2    = (const float*)d_in[12];
    const float* ln1_g = (const float*)d_in[13];
    const float* ln1_b = (const float*)d_in[14];
    const float* ln2_g = (const float*)d_in[15];
    const float* ln2_b = (const float*)d_in[16];
    float* out = (float*)d_out;

    float *p_ln, *p_qkv, *p_attn, *p_ff, *p_wqkv, *p_bqkv;
    cudaGetSymbolAddress((void**)&p_ln,   g_ln);
    cudaGetSymbolAddress((void**)&p_qkv,  g_qkv);
    cudaGetSymbolAddress((void**)&p_attn, g_attn);
    cudaGetSymbolAddress((void**)&p_ff,   g_ff);
    cudaGetSymbolAddress((void**)&p_wqkv, g_wqkv);
    cudaGetSymbolAddress((void**)&p_bqkv, g_bqkv);

    cudaFuncSetAttribute(attn_tc_kernel,
                         cudaFuncAttributeMaxDynamicSharedMemorySize,
                         SM_ATTN_BYTES);

    // 1. pack qkv weights
    pack_qkv_kernel<<<(EMBED * NQKV + 255) / 256, 256>>>(
        Wq, Wk, Wv, bq, bk, bv, p_wqkv, p_bqkv);

    // 2. LN1
    ln_kernel<<<ROWS, EMBED>>>(x, ln1_g, ln1_b, p_ln);

    // 3. QKV projection (tf32 tensor cores)
    {
        dim3 g(NQKV / 128, ROWS / 128);
        gemm_tf32<false><<<g, 256>>>(p_ln, p_wqkv, p_bqkv, nullptr, p_qkv,
                                     NQKV, EMBED);
    }

    // 4. causal attention (tf32 tensor cores)
    attn_tc_kernel<<<dim3(2, HEADS, BATCH), 256, SM_ATTN_BYTES>>>(
        p_qkv, p_attn);

    // 5. output projection + residual
    {
        dim3 g(EMBED / 128, ROWS / 128);
        gemm_tf32<false><<<g, 256>>>(p_attn, Wp, bp, x, out, EMBED, EMBED);
    }

    // 6. LN2
    ln_kernel<<<ROWS, EMBED>>>(out, ln2_g, ln2_b, p_ln);

    // 7. FFN layer 1 (relu)
    {
        dim3 g(EMBED / 128, ROWS / 128);
        gemm_tf32<true><<<g, 256>>>(p_ln, W1, b1, nullptr, p_ff, EMBED, EMBED);
    }

    // 8. FFN layer 2 + residual
    {
        dim3 g(EMBED / 128, ROWS / 128);
        gemm_tf32<false><<<g, 256>>>(p_ff, W2, b2, out, out, EMBED, EMBED);
    }
}

// round 10
// speedup vs baseline: 2.4828x; 1.0041x over previous
#include <cuda_runtime.h>
#include <math.h>
#include <stdint.h>

#define EMBED 384
#define HEADS 6
#define HS    64
#define BATCH 64
#define SEQ   256
#define ROWS  (BATCH*SEQ)     // 16384
#define NQKV  (3*EMBED)       // 1152

// ------------------------- device scratch (no allocs allowed) ----------------
__device__ float  g_qkv [ROWS*NQKV];
__device__ float  g_attn[ROWS*EMBED];
__device__ float  g_ff  [ROWS*EMBED];
__device__ float  g_wqkv[EMBED*NQKV];
__device__ float  g_bqkv[NQKV];
__device__ float2 g_stats[ROWS];

// ------------------------- helpers ------------------------------------------
__device__ __forceinline__ uint32_t f2tf32(float x) {
    uint32_t r;
    asm("cvt.rna.tf32.f32 %0, %1;" : "=r"(r) : "f"(x));
    return r;
}

__device__ __forceinline__ void mma_tf32(float d[4], const uint32_t a[4],
                                         const uint32_t b[2]) {
    asm volatile(
        "mma.sync.aligned.m16n8k8.row.col.f32.tf32.tf32.f32 "
        "{%0,%1,%2,%3}, {%4,%5,%6,%7}, {%8,%9}, {%0,%1,%2,%3};\n"
        : "+f"(d[0]), "+f"(d[1]), "+f"(d[2]), "+f"(d[3])
        : "r"(a[0]), "r"(a[1]), "r"(a[2]), "r"(a[3]), "r"(b[0]), "r"(b[1]));
}

__device__ __forceinline__ void cp_async16(uint32_t saddr, const void* g) {
    asm volatile("cp.async.cg.shared.global [%0], [%1], 16;"
                 :: "r"(saddr), "l"(g));
}
#define CP_COMMIT() asm volatile("cp.async.commit_group;")
#define CP_WAIT0()  asm volatile("cp.async.wait_group 0;")

// ------------------------- weight repack: [H,C,D]x3 -> [C, 3*H*D] ------------
__global__ void pack_qkv_kernel(const float* __restrict__ Wq,
                                const float* __restrict__ Wk,
                                const float* __restrict__ Wv,
                                const float* __restrict__ bq,
                                const float* __restrict__ bk,
                                const float* __restrict__ bv,
                                float* __restrict__ Wout,
                                float* __restrict__ bout) {
    int idx = blockIdx.x * 256 + threadIdx.x;
    if (idx < EMBED * NQKV) {
        int c   = idx / NQKV;
        int n   = idx % NQKV;
        int sel = n / EMBED;
        int hd  = n % EMBED;
        int h   = hd / HS;
        int d   = hd % HS;
        const float* W = (sel == 0) ? Wq : (sel == 1) ? Wk : Wv;
        Wout[idx] = W[((size_t)h * EMBED + c) * HS + d];
    }
    if (idx < NQKV) {
        int sel = idx / EMBED;
        int hd  = idx % EMBED;
        const float* bb = (sel == 0) ? bq : (sel == 1) ? bk : bv;
        bout[idx] = bb[hd];
    }
}

// ------------------------- LN stats: per-row mean / rstd ---------------------
__global__ __launch_bounds__(256)
void ln_stats_kernel(const float* __restrict__ x, float2* __restrict__ st) {
    int row  = blockIdx.x * 8 + (threadIdx.x >> 5);
    int lane = threadIdx.x & 31;
    const float4* xr = reinterpret_cast<const float4*>(x + (size_t)row * EMBED);
    float s = 0.f, s2 = 0.f;
    #pragma unroll
    for (int i = 0; i < 3; i++) {
        float4 v = xr[lane + 32 * i];
        s  += v.x + v.y + v.z + v.w;
        s2 += v.x * v.x + v.y * v.y + v.z * v.z + v.w * v.w;
    }
    #pragma unroll
    for (int o = 16; o; o >>= 1) {
        s  += __shfl_xor_sync(0xffffffffu, s,  o);
        s2 += __shfl_xor_sync(0xffffffffu, s2, o);
    }
    if (lane == 0) {
        float mu  = s * (1.0f / EMBED);
        float var = s2 * (1.0f / EMBED) - mu * mu;
        st[row] = make_float2(mu, rsqrtf(var + 1e-5f));
    }
}

// ------------------------- TF32 GEMM, double-buffered, optional fused LN -----
// C[M,N] = A'[M,K] @ B[K,N] (+bias, opt relu, opt residual)
// A' = LN ? (A - mu)*rstd*g + b : A
#define A_PITCH 36
#define B_PITCH 136
#define G_STAGE (128*A_PITCH + 32*B_PITCH)           // u32 per stage (8960)
#define SM_GEMM_BYTES (2 * G_STAGE * 4)              // 71680

template<bool LN, bool RELU>
__global__ __launch_bounds__(256)
void gemm_tf32(const float* __restrict__ A, const float* __restrict__ Bm,
               const float* __restrict__ bias, const float* __restrict__ res,
               float* __restrict__ C, int N, int K,
               const float2* __restrict__ stats,
               const float* __restrict__ lng, const float* __restrict__ lnb) {
    extern __shared__ uint32_t gsh[];

    const int tid  = threadIdx.x;
    const int bm   = blockIdx.y * 128;
    const int bn   = blockIdx.x * 128;
    const int warp = tid >> 5;
    const int lane = tid & 31;
    const int wm   = (warp >> 2) * 64;
    const int wn   = (warp & 3) * 32;
    const int gid  = lane >> 2;
    const int tig  = lane & 3;

    float acc[4][4][4];
    #pragma unroll
    for (int i = 0; i < 4; i++)
        #pragma unroll
        for (int j = 0; j < 4; j++)
            #pragma unroll
            for (int r = 0; r < 4; r++) acc[i][j][r] = 0.f;

    float4 aS[4], bS[4];
    const int a_r  = tid >> 3;
    const int a_k4 = (tid & 7) * 4;
    const int b_k  = tid >> 5;
    const int b_n4 = (tid & 31) * 4;

    auto ldg_tile = [&](int kt) {
        const int k0 = kt * 32;
        float4 gv, bv4;
        if (LN) {
            gv  = *reinterpret_cast<const float4*>(&lng[k0 + a_k4]);
            bv4 = *reinterpret_cast<const float4*>(&lnb[k0 + a_k4]);
        }
        #pragma unroll
        for (int it = 0; it < 4; it++) {
            int r = a_r + it * 32;
            float4 v = *reinterpret_cast<const float4*>(
                &A[(size_t)(bm + r) * K + k0 + a_k4]);
            if (LN) {
                float2 st = stats[bm + r];
                v.x = fmaf((v.x - st.x) * st.y, gv.x, bv4.x);
                v.y = fmaf((v.y - st.x) * st.y, gv.y, bv4.y);
                v.z = fmaf((v.z - st.x) * st.y, gv.z, bv4.z);
                v.w = fmaf((v.w - st.x) * st.y, gv.w, bv4.w);
            }
            aS[it] = v;
        }
        #pragma unroll
        for (int it = 0; it < 4; it++) {
            int kr = b_k + it * 8;
            bS[it] = *reinterpret_cast<const float4*>(
                &Bm[(size_t)(k0 + kr) * N + bn + b_n4]);
        }
    };

    auto sts_tile = [&](uint32_t* As, uint32_t* Bs) {
        #pragma unroll
        for (int it = 0; it < 4; it++) {
            int r = a_r + it * 32;
            uint4 u;
            u.x = f2tf32(aS[it].x); u.y = f2tf32(aS[it].y);
            u.z = f2tf32(aS[it].z); u.w = f2tf32(aS[it].w);
            *reinterpret_cast<uint4*>(&As[r * A_PITCH + a_k4]) = u;
        }
        #pragma unroll
        for (int it = 0; it < 4; it++) {
            int kr = b_k + it * 8;
            uint4 u;
            u.x = f2tf32(bS[it].x); u.y = f2tf32(bS[it].y);
            u.z = f2tf32(bS[it].z); u.w = f2tf32(bS[it].w);
            *reinterpret_cast<uint4*>(&Bs[kr * B_PITCH + b_n4]) = u;
        }
    };

    const int NT = K / 32;
    ldg_tile(0);
    sts_tile(gsh, gsh + 128 * A_PITCH);
    if (NT > 1) ldg_tile(1);
    __syncthreads();

    for (int kt = 0; kt < NT; kt++) {
        const int cur = kt & 1;
        uint32_t* Asc = gsh + cur * G_STAGE;
        uint32_t* Bsc = Asc + 128 * A_PITCH;
        if (kt + 1 < NT) {
            uint32_t* Asn = gsh + (cur ^ 1) * G_STAGE;
            sts_tile(Asn, Asn + 128 * A_PITCH);
        }
        if (kt + 2 < NT) ldg_tile(kt + 2);

        #pragma unroll
        for (int ks = 0; ks < 4; ks++) {
            uint32_t af[4][4];
            #pragma unroll
            for (int mi = 0; mi < 4; mi++) {
                int row  = wm + mi * 16 + gid;
                int base = row * A_PITCH + ks * 8 + tig;
                af[mi][0] = Asc[base];
                af[mi][2] = Asc[base + 4];
                af[mi][1] = Asc[base + 8 * A_PITCH];
                af[mi][3] = Asc[base + 8 * A_PITCH + 4];
            }
            uint32_t bf[4][2];
            #pragma unroll
            for (int nj = 0; nj < 4; nj++) {
                int col = wn + nj * 8 + gid;
                bf[nj][0] = Bsc[(ks * 8 + tig)     * B_PITCH + col];
                bf[nj][1] = Bsc[(ks * 8 + tig + 4) * B_PITCH + col];
            }
            #pragma unroll
            for (int mi = 0; mi < 4; mi++)
                #pragma unroll
                for (int nj = 0; nj < 4; nj++)
                    mma_tf32(acc[mi][nj], af[mi], bf[nj]);
        }
        __syncthreads();
    }

    #pragma unroll
    for (int mi = 0; mi < 4; mi++) {
        int row = bm + wm + mi * 16 + gid;
        #pragma unroll
        for (int nj = 0; nj < 4; nj++) {
            int col = bn + wn + nj * 8 + tig * 2;
            float2 bv = *reinterpret_cast<const float2*>(&bias[col]);
            float v0 = acc[mi][nj][0] + bv.x;
            float v1 = acc[mi][nj][1] + bv.y;
            float v2 = acc[mi][nj][2] + bv.x;
            float v3 = acc[mi][nj][3] + bv.y;
            if (RELU) {
                v0 = fmaxf(v0, 0.f); v1 = fmaxf(v1, 0.f);
                v2 = fmaxf(v2, 0.f); v3 = fmaxf(v3, 0.f);
            }
            if (res) {
                float2 r0 = *reinterpret_cast<const float2*>(
                    &res[(size_t)row * N + col]);
                float2 r1 = *reinterpret_cast<const float2*>(
                    &res[(size_t)(row + 8) * N + col]);
                v0 += r0.x; v1 += r0.y; v2 += r1.x; v3 += r1.y;
            }
            *reinterpret_cast<float2*>(&C[(size_t)row * N + col]) =
                make_float2(v0, v1);
            *reinterpret_cast<float2*>(&C[(size_t)(row + 8) * N + col]) =
                make_float2(v2, v3);
        }
    }
}

// ------------------------- tensor-core flash attention ----------------------
// CTA: 128 q-rows of one (b,h). 8 warps, warp-local softmax over 16 rows.
// K tiles: cp.async double-buffered (raw fp32 bits -> tf32 truncation).
// V tiles: register-staged prefetch, RN-converted + transposed STS.
#define QP 68
#define SM_ATTN_BYTES ((128*QP + 2*64*QP + 2*64*QP) * 4)   // 104448

__global__ __launch_bounds__(256)
void attn_tc_kernel(const float* __restrict__ qkv, float* __restrict__ out) {
    extern __shared__ uint32_t sh[];
    uint32_t* Qs  = sh;                          // [128][QP]
    uint32_t* Kb0 = sh + 128 * QP;               // 2 stages of [64][QP]
    uint32_t* Vb0 = sh + 128 * QP + 2 * 64 * QP; // 2 stages of [64][QP] (transposed)

    const int qt  = 1 - blockIdx.x;              // heavy tile first
    const int h   = blockIdx.y;
    const int b   = blockIdx.z;
    const int q0  = qt * 128;
    const int tid  = threadIdx.x;
    const int warp = tid >> 5;
    const int lane = tid & 31;
    const int gid  = lane >> 2;
    const int tig  = lane & 3;
    const int wr0  = warp * 16;
    const float qscale = rsqrtf((float)EMBED) * 1.4426950408889634f;

    // ---- load Q tile (tf32 RN, pre-scaled) ----
    #pragma unroll
    for (int it = 0; it < 8; it++) {
        int li = tid + it * 256;
        int r  = li >> 4;
        int d4 = (li & 15) * 4;
        float4 v = *reinterpret_cast<const float4*>(
            &qkv[(size_t)(b * SEQ + q0 + r) * NQKV + h * HS + d4]);
        uint4 u;
        u.x = f2tf32(v.x * qscale); u.y = f2tf32(v.y * qscale);
        u.z = f2tf32(v.z * qscale); u.w = f2tf32(v.w * qscale);
        *reinterpret_cast<uint4*>(&Qs[r * QP + d4]) = u;
    }

    // ---- prefetch machinery ----
    const uint32_t kb_addr = (uint32_t)__cvta_generic_to_shared(Kb0);
    auto cpk = [&](int st, int stage) {
        const float* base = &qkv[(size_t)(b * SEQ + st * 64) * NQKV + EMBED + h * HS];
        uint32_t dst = kb_addr + (uint32_t)(stage * 64 * QP) * 4u;
        #pragma unroll
        for (int it = 0; it < 4; it++) {
            int cid = tid + it * 256;        // 0..1023 16B chunks
            int r   = cid >> 4;              // 64 rows, 16 chunks per row
            int d4  = (cid & 15) * 4;        // 64 floats per row
            cp_async16(dst + (uint32_t)(r * QP + d4) * 4u,
                       base + (size_t)r * NQKV + d4);
        }
        CP_COMMIT();
    };
    float4 vS[4];
    auto ldgv = [&](int st) {
        #pragma unroll
        for (int it = 0; it < 4; it++) {
            int li = tid + it * 256;
            int s  = li & 63;
            int d4 = (li >> 6) * 4;
            vS[it] = *reinterpret_cast<const float4*>(
                &qkv[(size_t)(b * SEQ + st * 64 + s) * NQKV + 2 * EMBED + h * HS + d4]);
        }
    };
    auto stsv = [&](uint32_t* Vt) {
        #pragma unroll
        for (int it = 0; it < 4; it++) {
            int li = tid + it * 256;
            int s  = li & 63;
            int d4 = (li >> 6) * 4;
            Vt[(d4 + 0) * QP + s] = f2tf32(vS[it].x);
            Vt[(d4 + 1) * QP + s] = f2tf32(vS[it].y);
            Vt[(d4 + 2) * QP + s] = f2tf32(vS[it].z);
            Vt[(d4 + 3) * QP + s] = f2tf32(vS[it].w);
        }
    };

    float oacc[8][4];
    #pragma unroll
    for (int i = 0; i < 8; i++)
        #pragma unroll
        for (int j = 0; j < 4; j++) oacc[i][j] = 0.f;
    float m0 = -1e30f, m1 = -1e30f, l0 = 0.f, l1 = 0.f;

    const int nst = q0 / 64 + 2;

    cpk(0, 0);
    ldgv(0);

    for (int st = 0; st < nst; st++) {
        const int cur = st & 1;
        uint32_t* Ks = Kb0 + cur * 64 * QP;
        uint32_t* Vt = Vb0 + cur * 64 * QP;

        __syncthreads();                 // prev iter compute done (+Q on st=0)
        stsv(Vt);                        // tile st V (RN tf32, transposed)
        CP_WAIT0();                      // tile st K arrived
        __syncthreads();                 // K/V visible to all warps
        if (st + 1 < nst) {
            cpk(st + 1, cur ^ 1);
            ldgv(st + 1);
        }

        // ---- S = Q K^T ----
        float sacc[8][4];
        #pragma unroll
        for (int i = 0; i < 8; i++)
            #pragma unroll
            for (int j = 0; j < 4; j++) sacc[i][j] = 0.f;

        #pragma unroll
        for (int ks = 0; ks < 8; ks++) {
            uint32_t qa[4];
            int qb = (wr0 + gid) * QP + ks * 8 + tig;
            qa[0] = Qs[qb];
            qa[1] = Qs[qb + 8 * QP];
            qa[2] = Qs[qb + 4];
            qa[3] = Qs[qb + 8 * QP + 4];
            #pragma unroll
            for (int nt = 0; nt < 8; nt++) {
                uint32_t bk[2];
                int kb = (nt * 8 + gid) * QP + ks * 8 + tig;
                bk[0] = Ks[kb];
                bk[1] = Ks[kb + 4];
                mma_tf32(sacc[nt], qa, bk);
            }
        }

        // ---- causal mask ----
        const int r0g = q0 + wr0 + gid;
        const int r1g = r0g + 8;
        if (st * 64 + 63 > r0g - gid) {
            #pragma unroll
            for (int nt = 0; nt < 8; nt++) {
                int cb = st * 64 + nt * 8 + 2 * tig;
                if (cb     > r0g) sacc[nt][0] = -1e30f;
                if (cb + 1 > r0g) sacc[nt][1] = -1e30f;
                if (cb     > r1g) sacc[nt][2] = -1e30f;
                if (cb + 1 > r1g) sacc[nt][3] = -1e30f;
            }
        }

        // ---- online softmax (base 2) ----
        float mx0 = -1e30f, mx1 = -1e30f;
        #pragma unroll
        for (int nt = 0; nt < 8; nt++) {
            mx0 = fmaxf(mx0, fmaxf(sacc[nt][0], sacc[nt][1]));
            mx1 = fmaxf(mx1, fmaxf(sacc[nt][2], sacc[nt][3]));
        }
        #pragma unroll
        for (int o = 1; o <= 2; o <<= 1) {
            mx0 = fmaxf(mx0, __shfl_xor_sync(0xffffffffu, mx0, o));
            mx1 = fmaxf(mx1, __shfl_xor_sync(0xffffffffu, mx1, o));
        }
        float mn0 = fmaxf(m0, mx0), mn1 = fmaxf(m1, mx1);
        float al0 = exp2f(m0 - mn0), al1 = exp2f(m1 - mn1);
        m0 = mn0; m1 = mn1;

        float ls0 = 0.f, ls1 = 0.f;
        #pragma unroll
        for (int nt = 0; nt < 8; nt++) {
            float p0 = exp2f(sacc[nt][0] - mn0);
            float p1 = exp2f(sacc[nt][1] - mn0);
            float p2 = exp2f(sacc[nt][2] - mn1);
            float p3 = exp2f(sacc[nt][3] - mn1);
            sacc[nt][0] = p0; sacc[nt][1] = p1;
            sacc[nt][2] = p2; sacc[nt][3] = p3;
            ls0 += p0 + p1; ls1 += p2 + p3;
        }
        l0 = l0 * al0 + ls0;
        l1 = l1 * al1 + ls1;
        #pragma unroll
        for (int dn = 0; dn < 8; dn++) {
            oacc[dn][0] *= al0; oacc[dn][1] *= al0;
            oacc[dn][2] *= al1; oacc[dn][3] *= al1;
        }

        // ---- O += P @ V (P rearranged c-layout -> a-frag via quad shuffles) --
        const int s0l = 4 * gid + (tig >> 1);
        const bool odd = tig & 1;
        #pragma unroll
        for (int kc = 0; kc < 8; kc++) {
            float v00 = __shfl_sync(0xffffffffu, sacc[kc][0], s0l);
            float v01 = __shfl_sync(0xffffffffu, sacc[kc][1], s0l);
            float v10 = __shfl_sync(0xffffffffu, sacc[kc][2], s0l);
            float v11 = __shfl_sync(0xffffffffu, sacc[kc][3], s0l);
            float v20 = __shfl_sync(0xffffffffu, sacc[kc][0], s0l + 2);
            float v21 = __shfl_sync(0xffffffffu, sacc[kc][1], s0l + 2);
            float v30 = __shfl_sync(0xffffffffu, sacc[kc][2], s0l + 2);
            float v31 = __shfl_sync(0xffffffffu, sacc[kc][3], s0l + 2);
            uint32_t pa[4];
            pa[0] = f2tf32(odd ? v01 : v00);
            pa[1] = f2tf32(odd ? v11 : v10);
            pa[2] = f2tf32(odd ? v21 : v20);
            pa[3] = f2tf32(odd ? v31 : v30);
            #pragma unroll
            for (int dn = 0; dn < 8; dn++) {
                uint32_t bv[2];
                int vb = (dn * 8 + gid) * QP + kc * 8 + tig;
                bv[0] = Vt[vb];
                bv[1] = Vt[vb + 4];
                mma_tf32(oacc[dn], pa, bv);
            }
        }
    }

    // ---- finalize ----
    #pragma unroll
    for (int o = 1; o <= 2; o <<= 1) {
        l0 += __shfl_xor_sync(0xffffffffu, l0, o);
        l1 += __shfl_xor_sync(0xffffffffu, l1, o);
    }
    float inv0 = 1.f / l0, inv1 = 1.f / l1;
    const int row0 = b * SEQ + q0 + wr0 + gid;
    #pragma unroll
    for (int dn = 0; dn < 8; dn++) {
        int col = h * HS + dn * 8 + 2 * tig;
        *reinterpret_cast<float2*>(&out[(size_t)row0 * EMBED + col]) =
            make_float2(oacc[dn][0] * inv0, oacc[dn][1] * inv0);
        *reinterpret_cast<float2*>(&out[(size_t)(row0 + 8) * EMBED + col]) =
            make_float2(oacc[dn][2] * inv1, oacc[dn][3] * inv1);
    }
}

// ------------------------- launch ------------------------------------------
extern "C" void kernel_launch(void* const* d_in, const int* in_sizes, int n_in,
                              void* d_out, int out_size) {
    (void)in_sizes; (void)n_in; (void)out_size;
    const float* x     = (const float*)d_in[0];
    const float* Wq    = (const float*)d_in[1];
    const float* bq    = (const float*)d_in[2];
    const float* Wk    = (const float*)d_in[3];
    const float* bk    = (const float*)d_in[4];
    const float* Wv    = (const float*)d_in[5];
    const float* bv    = (const float*)d_in[6];
    const float* Wp    = (const float*)d_in[7];
    const float* bp    = (const float*)d_in[8];
    const float* W1    = (const float*)d_in[9];
    const float* b1    = (const float*)d_in[10];
    const float* W2    = (const float*)d_in[11];
    const float* b2    = (const float*)d_in[12];
    const float* ln1_g = (const float*)d_in[13];
    const float* ln1_b = (const float*)d_in[14];
    const float* ln2_g = (const float*)d_in[15];
    const float* ln2_b = (const float*)d_in[16];
    float* out = (float*)d_out;

    float *p_qkv, *p_attn, *p_ff, *p_wqkv, *p_bqkv;
    float2* p_stats;
    cudaGetSymbolAddress((void**)&p_qkv,  g_qkv);
    cudaGetSymbolAddress((void**)&p_attn, g_attn);
    cudaGetSymbolAddress((void**)&p_ff,   g_ff);
    cudaGetSymbolAddress((void**)&p_wqkv, g_wqkv);
    cudaGetSymbolAddress((void**)&p_bqkv, g_bqkv);
    cudaGetSymbolAddress((void**)&p_stats, g_stats);

    cudaFuncSetAttribute(attn_tc_kernel,
                         cudaFuncAttributeMaxDynamicSharedMemorySize,
                         SM_ATTN_BYTES);
    cudaFuncSetAttribute(gemm_tf32<true,  false>,
                         cudaFuncAttributeMaxDynamicSharedMemorySize,
                         SM_GEMM_BYTES);
    cudaFuncSetAttribute(gemm_tf32<false, false>,
                         cudaFuncAttributeMaxDynamicSharedMemorySize,
                         SM_GEMM_BYTES);
    cudaFuncSetAttribute(gemm_tf32<true,  true>,
                         cudaFuncAttributeMaxDynamicSharedMemorySize,
                         SM_GEMM_BYTES);

    // 1. pack qkv weights
    pack_qkv_kernel<<<(EMBED * NQKV + 255) / 256, 256>>>(
        Wq, Wk, Wv, bq, bk, bv, p_wqkv, p_bqkv);

    // 2. LN1 stats
    ln_stats_kernel<<<ROWS / 8, 256>>>(x, p_stats);

    // 3. QKV projection with fused LN1
    {
        dim3 g(NQKV / 128, ROWS / 128);
        gemm_tf32<true, false><<<g, 256, SM_GEMM_BYTES>>>(
            x, p_wqkv, p_bqkv, nullptr, p_qkv, NQKV, EMBED,
            p_stats, ln1_g, ln1_b);
    }

    // 4. causal attention
    attn_tc_kernel<<<dim3(2, HEADS, BATCH), 256, SM_ATTN_BYTES>>>(
        p_qkv, p_attn);

    // 5. output projection + residual
    {
        dim3 g(EMBED / 128, ROWS / 128);
        gemm_tf32<false, false><<<g, 256, SM_GEMM_BYTES>>>(
            p_attn, Wp, bp, x, out, EMBED, EMBED, nullptr, nullptr, nullptr);
    }

    // 6. LN2 stats
    ln_stats_kernel<<<ROWS / 8, 256>>>(out, p_stats);

    // 7. FFN layer 1 with fused LN2 + relu
    {
        dim3 g(EMBED / 128, ROWS / 128);
        gemm_tf32<true, true><<<g, 256, SM_GEMM_BYTES>>>(
            out, W1, b1, nullptr, p_ff, EMBED, EMBED,
            p_stats, ln2_g, ln2_b);
    }

    // 8. FFN layer 2 + residual
    {
        dim3 g(EMBED / 128, ROWS / 128);
        gemm_tf32<false, false><<<g, 256, SM_GEMM_BYTES>>>(
            p_ff, W2, b2, out, out, EMBED, EMBED, nullptr, nullptr, nullptr);
    }
}

// round 13
// speedup vs baseline: 3.3546x; 1.3512x over previous
#include <cuda_runtime.h>
#include <cuda_fp16.h>
#include <math.h>
#include <stdint.h>

#define EMBED 384
#define HEADS 6
#define HS    64
#define BATCH 64
#define SEQ   256
#define ROWS  (BATCH*SEQ)     // 16384
#define NQKV  (3*EMBED)       // 1152
#define KW    (EMBED/2)       // 192 k-words (half2)

// ------------------------- device scratch (no allocs allowed) ----------------
__device__ float    g_qkv   [ROWS*NQKV];
__device__ float    g_attn  [ROWS*EMBED];
__device__ float    g_ff    [ROWS*EMBED];
__device__ uint32_t g_wqkv16[KW*NQKV];    // half2 words, [k_word][n]
__device__ uint32_t g_wp16  [KW*EMBED];
__device__ uint32_t g_w116  [KW*EMBED];
__device__ uint32_t g_w216  [KW*EMBED];
__device__ float    g_bqkv  [NQKV];
__device__ float2   g_stats [ROWS];

// ------------------------- helpers ------------------------------------------
__device__ __forceinline__ uint32_t f2tf32(float x) {
    uint32_t r;
    asm("cvt.rna.tf32.f32 %0, %1;" : "=r"(r) : "f"(x));
    return r;
}

__device__ __forceinline__ uint32_t pack_half2(float a, float b) {
    __half2 h = __floats2half2_rn(a, b);
    return *reinterpret_cast<uint32_t*>(&h);
}

__device__ __forceinline__ void mma_tf32(float d[4], const uint32_t a[4],
                                         const uint32_t b[2]) {
    asm volatile(
        "mma.sync.aligned.m16n8k8.row.col.f32.tf32.tf32.f32 "
        "{%0,%1,%2,%3}, {%4,%5,%6,%7}, {%8,%9}, {%0,%1,%2,%3};\n"
        : "+f"(d[0]), "+f"(d[1]), "+f"(d[2]), "+f"(d[3])
        : "r"(a[0]), "r"(a[1]), "r"(a[2]), "r"(a[3]), "r"(b[0]), "r"(b[1]));
}

__device__ __forceinline__ void mma_f16(float d[4], const uint32_t a[4],
                                        const uint32_t b[2]) {
    asm volatile(
        "mma.sync.aligned.m16n8k16.row.col.f32.f16.f16.f32 "
        "{%0,%1,%2,%3}, {%4,%5,%6,%7}, {%8,%9}, {%0,%1,%2,%3};\n"
        : "+f"(d[0]), "+f"(d[1]), "+f"(d[2]), "+f"(d[3])
        : "r"(a[0]), "r"(a[1]), "r"(a[2]), "r"(a[3]), "r"(b[0]), "r"(b[1]));
}

__device__ __forceinline__ void cp_async16(uint32_t saddr, const void* g) {
    asm volatile("cp.async.cg.shared.global [%0], [%1], 16;"
                 :: "r"(saddr), "l"(g));
}
#define CP_COMMIT() asm volatile("cp.async.commit_group;")
#define CP_WAIT0()  asm volatile("cp.async.wait_group 0;")

__device__ __forceinline__ uint32_t smem_u32(const void* p) {
    return (uint32_t)__cvta_generic_to_shared(p);
}

// ------------------------- weight packing (half2 word layout) ---------------
__global__ void pack_qkv16_kernel(const float* __restrict__ Wq,
                                  const float* __restrict__ Wk,
                                  const float* __restrict__ Wv,
                                  const float* __restrict__ bq,
                                  const float* __restrict__ bk,
                                  const float* __restrict__ bv,
                                  uint32_t* __restrict__ Wt,
                                  float* __restrict__ bout) {
    int idx = blockIdx.x * 256 + threadIdx.x;
    if (idx < KW * NQKV) {
        int w   = idx / NQKV;        // k-word (c pair)
        int n   = idx % NQKV;
        int sel = n / EMBED;
        int hd  = n % EMBED;
        int h   = hd / HS;
        int d   = hd % HS;
        const float* W = (sel == 0) ? Wq : (sel == 1) ? Wk : Wv;
        float v0 = W[((size_t)h * EMBED + 2 * w)     * HS + d];
        float v1 = W[((size_t)h * EMBED + 2 * w + 1) * HS + d];
        Wt[idx] = pack_half2(v0, v1);
    }
    if (idx < NQKV) {
        int sel = idx / EMBED;
        int hd  = idx % EMBED;
        const float* bb = (sel == 0) ? bq : (sel == 1) ? bk : bv;
        bout[idx] = bb[hd];
    }
}

__global__ void pack_w16_kernel(const float* __restrict__ W,
                                uint32_t* __restrict__ Wt) {
    int idx = blockIdx.x * 256 + threadIdx.x;
    if (idx < KW * EMBED) {
        int w = idx / EMBED;
        int n = idx % EMBED;
        Wt[idx] = pack_half2(W[(size_t)(2 * w) * EMBED + n],
                             W[(size_t)(2 * w + 1) * EMBED + n]);
    }
}

// ------------------------- LN stats ------------------------------------------
__global__ __launch_bounds__(256)
void ln_stats_kernel(const float* __restrict__ x, float2* __restrict__ st) {
    int row  = blockIdx.x * 8 + (threadIdx.x >> 5);
    int lane = threadIdx.x & 31;
    const float4* xr = reinterpret_cast<const float4*>(x + (size_t)row * EMBED);
    float s = 0.f, s2 = 0.f;
    #pragma unroll
    for (int i = 0; i < 3; i++) {
        float4 v = xr[lane + 32 * i];
        s  += v.x + v.y + v.z + v.w;
        s2 += v.x * v.x + v.y * v.y + v.z * v.z + v.w * v.w;
    }
    #pragma unroll
    for (int o = 16; o; o >>= 1) {
        s  += __shfl_xor_sync(0xffffffffu, s,  o);
        s2 += __shfl_xor_sync(0xffffffffu, s2, o);
    }
    if (lane == 0) {
        float mu  = s * (1.0f / EMBED);
        float var = s2 * (1.0f / EMBED) - mu * mu;
        st[row] = make_float2(mu, rsqrtf(var + 1e-5f));
    }
}

// ------------------------- FP16 tensor-core GEMM ----------------------------
// C[M,N] = A'[M,384] @ B[384,N] (+bias, opt relu, opt residual)
// A' = LN ? layernorm(A) : A (f32 in gmem, converted RN to half on STS).
// B pre-packed half2 words [k_word][n].  CTA 128x128, k-tile 64 (=32 words),
// 6 k-tiles, double-buffered, one sync per tile. mma m16n8k16 f16, f32 accum.
#define A_PITCH 36     // words; frag addr mod 32 = 4*gid + tig -> conflict-free
#define B_PITCH 136    // words; 136 mod 32 = 8 -> 8*tig + gid -> conflict-free
#define AS_WORDS (128 * A_PITCH)                 // 4608
#define BS_WORDS (32 * B_PITCH)                  // 4352
#define STG_WORDS (AS_WORDS + BS_WORDS)          // 8960
#define SM_GEMM_BYTES (2 * STG_WORDS * 4)        // 71680

template<bool LN, bool RELU>
__global__ __launch_bounds__(256)
void gemm_f16(const float* __restrict__ A, const uint32_t* __restrict__ Bw,
              const float* __restrict__ bias, const float* __restrict__ res,
              float* __restrict__ C, int N,
              const float2* __restrict__ stats,
              const float* __restrict__ lng, const float* __restrict__ lnb) {
    extern __shared__ uint32_t gsh[];
    const uint32_t smb = smem_u32(gsh);

    const int tid  = threadIdx.x;
    const int bm   = blockIdx.y * 128;
    const int bn   = blockIdx.x * 128;
    const int warp = tid >> 5;
    const int lane = tid & 31;
    const int wm   = (warp >> 2) * 64;
    const int wn   = (warp & 3) * 32;
    const int gid  = lane >> 2;
    const int tig  = lane & 3;

    float acc[4][4][4];
    #pragma unroll
    for (int i = 0; i < 4; i++)
        #pragma unroll
        for (int j = 0; j < 4; j++)
            #pragma unroll
            for (int r = 0; r < 4; r++) acc[i][j][r] = 0.f;

    // A staging: 8 chunks of float4 -> 2 half2 words each
    uint2 aS[8];
    const int a_row = tid >> 4;          // 0..15 (+16*it)
    const int a_f4  = tid & 15;          // float4 index within 64-float row

    auto ldgA = [&](int kt) {
        const int k0 = kt * 64;
        float4 gv, bv4;
        if (LN) {
            gv  = *reinterpret_cast<const float4*>(&lng[k0 + a_f4 * 4]);
            bv4 = *reinterpret_cast<const float4*>(&lnb[k0 + a_f4 * 4]);
        }
        #pragma unroll
        for (int it = 0; it < 8; it++) {
            int r = a_row + it * 16;
            float4 v = *reinterpret_cast<const float4*>(
                &A[(size_t)(bm + r) * EMBED + k0 + a_f4 * 4]);
            if (LN) {
                float2 st = stats[bm + r];
                v.x = fmaf((v.x - st.x) * st.y, gv.x, bv4.x);
                v.y = fmaf((v.y - st.x) * st.y, gv.y, bv4.y);
                v.z = fmaf((v.z - st.x) * st.y, gv.z, bv4.z);
                v.w = fmaf((v.w - st.x) * st.y, gv.w, bv4.w);
            }
            aS[it].x = pack_half2(v.x, v.y);
            aS[it].y = pack_half2(v.z, v.w);
        }
    };
    auto stsA = [&](int s) {
        uint32_t* As = gsh + s * STG_WORDS;
        #pragma unroll
        for (int it = 0; it < 8; it++) {
            int r = a_row + it * 16;
            As[r * A_PITCH + a_f4 * 2]     = aS[it].x;
            As[r * A_PITCH + a_f4 * 2 + 1] = aS[it].y;
        }
    };
    const int b_kr = tid >> 5;           // 0..7 (+8*it)
    const int b_n4 = (tid & 31) * 4;
    auto cpB = [&](int kt, int s) {
        const int k0w = kt * 32;
        const uint32_t b_sm = smb + (s * STG_WORDS + AS_WORDS) * 4;
        #pragma unroll
        for (int it = 0; it < 4; it++) {
            int kr = b_kr + it * 8;
            cp_async16(b_sm + (uint32_t)(kr * B_PITCH + b_n4) * 4,
                       &Bw[(size_t)(k0w + kr) * N + bn + b_n4]);
        }
        CP_COMMIT();
    };

    const int NT = 6;
    cpB(0, 0);
    ldgA(0);
    stsA(0);
    ldgA(1);
    CP_WAIT0();
    __syncthreads();

    for (int kt = 0; kt < NT; kt++) {
        const int cur = kt & 1;
        uint32_t* Asc = gsh + cur * STG_WORDS;
        uint32_t* Bsc = Asc + AS_WORDS;

        if (kt + 1 < NT) {               // stage kt+1 into cur^1
            stsA(cur ^ 1);
            cpB(kt + 1, cur ^ 1);
        }
        if (kt + 2 < NT) ldgA(kt + 2);

        #pragma unroll
        for (int ks = 0; ks < 4; ks++) {
            uint32_t af[4][4];
            #pragma unroll
            for (int mi = 0; mi < 4; mi++) {
                int row  = wm + mi * 16 + gid;
                int base = row * A_PITCH + ks * 8 + tig;
                af[mi][0] = Asc[base];
                af[mi][2] = Asc[base + 4];
                af[mi][1] = Asc[base + 8 * A_PITCH];
                af[mi][3] = Asc[base + 8 * A_PITCH + 4];
            }
            uint32_t bf[4][2];
            #pragma unroll
            for (int nj = 0; nj < 4; nj++) {
                int col = wn + nj * 8 + gid;
                bf[nj][0] = Bsc[(ks * 8 + tig)     * B_PITCH + col];
                bf[nj][1] = Bsc[(ks * 8 + tig + 4) * B_PITCH + col];
            }
            #pragma unroll
            for (int mi = 0; mi < 4; mi++)
                #pragma unroll
                for (int nj = 0; nj < 4; nj++)
                    mma_f16(acc[mi][nj], af[mi], bf[nj]);
        }
        CP_WAIT0();
        __syncthreads();
    }

    // epilogue (c-frag layout of m16n8k16 == m16n8k8)
    #pragma unroll
    for (int mi = 0; mi < 4; mi++) {
        int row = bm + wm + mi * 16 + gid;
        #pragma unroll
        for (int nj = 0; nj < 4; nj++) {
            int col = bn + wn + nj * 8 + tig * 2;
            float2 bv = *reinterpret_cast<const float2*>(&bias[col]);
            float v0 = acc[mi][nj][0] + bv.x;
            float v1 = acc[mi][nj][1] + bv.y;
            float v2 = acc[mi][nj][2] + bv.x;
            float v3 = acc[mi][nj][3] + bv.y;
            if (RELU) {
                v0 = fmaxf(v0, 0.f); v1 = fmaxf(v1, 0.f);
                v2 = fmaxf(v2, 0.f); v3 = fmaxf(v3, 0.f);
            }
            if (res) {
                float2 r0 = *reinterpret_cast<const float2*>(
                    &res[(size_t)row * N + col]);
                float2 r1 = *reinterpret_cast<const float2*>(
                    &res[(size_t)(row + 8) * N + col]);
                v0 += r0.x; v1 += r0.y; v2 += r1.x; v3 += r1.y;
            }
            *reinterpret_cast<float2*>(&C[(size_t)row * N + col]) =
                make_float2(v0, v1);
            *reinterpret_cast<float2*>(&C[(size_t)(row + 8) * N + col]) =
                make_float2(v2, v3);
        }
    }
}

// ------------------------- tensor-core flash attention (unchanged R10) ------
#define QP 68
#define SM_ATTN_BYTES ((128*QP + 2*64*QP + 2*64*QP) * 4)   // 104448

__global__ __launch_bounds__(256)
void attn_tc_kernel(const float* __restrict__ qkv, float* __restrict__ out) {
    extern __shared__ uint32_t sh[];
    uint32_t* Qs  = sh;
    uint32_t* Kb0 = sh + 128 * QP;
    uint32_t* Vb0 = sh + 128 * QP + 2 * 64 * QP;

    const int qt  = 1 - blockIdx.x;
    const int h   = blockIdx.y;
    const int b   = blockIdx.z;
    const int q0  = qt * 128;
    const int tid  = threadIdx.x;
    const int warp = tid >> 5;
    const int lane = tid & 31;
    const int gid  = lane >> 2;
    const int tig  = lane & 3;
    const int wr0  = warp * 16;
    const float qscale = rsqrtf((float)EMBED) * 1.4426950408889634f;

    #pragma unroll
    for (int it = 0; it < 8; it++) {
        int li = tid + it * 256;
        int r  = li >> 4;
        int d4 = (li & 15) * 4;
        float4 v = *reinterpret_cast<const float4*>(
            &qkv[(size_t)(b * SEQ + q0 + r) * NQKV + h * HS + d4]);
        uint4 u;
        u.x = f2tf32(v.x * qscale); u.y = f2tf32(v.y * qscale);
        u.z = f2tf32(v.z * qscale); u.w = f2tf32(v.w * qscale);
        *reinterpret_cast<uint4*>(&Qs[r * QP + d4]) = u;
    }

    const uint32_t kb_addr = smem_u32(Kb0);
    auto cpk = [&](int st, int stage) {
        const float* base = &qkv[(size_t)(b * SEQ + st * 64) * NQKV + EMBED + h * HS];
        uint32_t dst = kb_addr + (uint32_t)(stage * 64 * QP) * 4u;
        #pragma unroll
        for (int it = 0; it < 4; it++) {
            int cid = tid + it * 256;
            int r   = cid >> 4;
            int d4  = (cid & 15) * 4;
            cp_async16(dst + (uint32_t)(r * QP + d4) * 4u,
                       base + (size_t)r * NQKV + d4);
        }
        CP_COMMIT();
    };
    float4 vS[4];
    auto ldgv = [&](int st) {
        #pragma unroll
        for (int it = 0; it < 4; it++) {
            int li = tid + it * 256;
            int s  = li & 63;
            int d4 = (li >> 6) * 4;
            vS[it] = *reinterpret_cast<const float4*>(
                &qkv[(size_t)(b * SEQ + st * 64 + s) * NQKV + 2 * EMBED + h * HS + d4]);
        }
    };
    auto stsv = [&](uint32_t* Vt) {
        #pragma unroll
        for (int it = 0; it < 4; it++) {
            int li = tid + it * 256;
            int s  = li & 63;
            int d4 = (li >> 6) * 4;
            Vt[(d4 + 0) * QP + s] = f2tf32(vS[it].x);
            Vt[(d4 + 1) * QP + s] = f2tf32(vS[it].y);
            Vt[(d4 + 2) * QP + s] = f2tf32(vS[it].z);
            Vt[(d4 + 3) * QP + s] = f2tf32(vS[it].w);
        }
    };

    float oacc[8][4];
    #pragma unroll
    for (int i = 0; i < 8; i++)
        #pragma unroll
        for (int j = 0; j < 4; j++) oacc[i][j] = 0.f;
    float m0 = -1e30f, m1 = -1e30f, l0 = 0.f, l1 = 0.f;

    const int nst = q0 / 64 + 2;
    cpk(0, 0);
    ldgv(0);

    for (int st = 0; st < nst; st++) {
        const int cur = st & 1;
        uint32_t* Ks = Kb0 + cur * 64 * QP;
        uint32_t* Vt = Vb0 + cur * 64 * QP;

        __syncthreads();
        stsv(Vt);
        CP_WAIT0();
        __syncthreads();
        if (st + 1 < nst) {
            cpk(st + 1, cur ^ 1);
            ldgv(st + 1);
        }

        float sacc[8][4];
        #pragma unroll
        for (int i = 0; i < 8; i++)
            #pragma unroll
            for (int j = 0; j < 4; j++) sacc[i][j] = 0.f;

        #pragma unroll
        for (int ks = 0; ks < 8; ks++) {
            uint32_t qa[4];
            int qb = (wr0 + gid) * QP + ks * 8 + tig;
            qa[0] = Qs[qb];
            qa[1] = Qs[qb + 8 * QP];
            qa[2] = Qs[qb + 4];
            qa[3] = Qs[qb + 8 * QP + 4];
            #pragma unroll
            for (int nt = 0; nt < 8; nt++) {
                uint32_t bk[2];
                int kb = (nt * 8 + gid) * QP + ks * 8 + tig;
                bk[0] = Ks[kb];
                bk[1] = Ks[kb + 4];
                mma_tf32(sacc[nt], qa, bk);
            }
        }

        const int r0g = q0 + wr0 + gid;
        const int r1g = r0g + 8;
        if (st * 64 + 63 > r0g - gid) {
            #pragma unroll
            for (int nt = 0; nt < 8; nt++) {
                int cb = st * 64 + nt * 8 + 2 * tig;
                if (cb     > r0g) sacc[nt][0] = -1e30f;
                if (cb + 1 > r0g) sacc[nt][1] = -1e30f;
                if (cb     > r1g) sacc[nt][2] = -1e30f;
                if (cb + 1 > r1g) sacc[nt][3] = -1e30f;
            }
        }

        float mx0 = -1e30f, mx1 = -1e30f;
        #pragma unroll
        for (int nt = 0; nt < 8; nt++) {
            mx0 = fmaxf(mx0, fmaxf(sacc[nt][0], sacc[nt][1]));
            mx1 = fmaxf(mx1, fmaxf(sacc[nt][2], sacc[nt][3]));
        }
        #pragma unroll
        for (int o = 1; o <= 2; o <<= 1) {
            mx0 = fmaxf(mx0, __shfl_xor_sync(0xffffffffu, mx0, o));
            mx1 = fmaxf(mx1, __shfl_xor_sync(0xffffffffu, mx1, o));
        }
        float mn0 = fmaxf(m0, mx0), mn1 = fmaxf(m1, mx1);
        float al0 = exp2f(m0 - mn0), al1 = exp2f(m1 - mn1);
        m0 = mn0; m1 = mn1;

        float ls0 = 0.f, ls1 = 0.f;
        #pragma unroll
        for (int nt = 0; nt < 8; nt++) {
            float p0 = exp2f(sacc[nt][0] - mn0);
            float p1 = exp2f(sacc[nt][1] - mn0);
            float p2 = exp2f(sacc[nt][2] - mn1);
            float p3 = exp2f(sacc[nt][3] - mn1);
            sacc[nt][0] = p0; sacc[nt][1] = p1;
            sacc[nt][2] = p2; sacc[nt][3] = p3;
            ls0 += p0 + p1; ls1 += p2 + p3;
        }
        l0 = l0 * al0 + ls0;
        l1 = l1 * al1 + ls1;
        #pragma unroll
        for (int dn = 0; dn < 8; dn++) {
            oacc[dn][0] *= al0; oacc[dn][1] *= al0;
            oacc[dn][2] *= al1; oacc[dn][3] *= al1;
        }

        const int s0l = 4 * gid + (tig >> 1);
        const bool odd = tig & 1;
        #pragma unroll
        for (int kc = 0; kc < 8; kc++) {
            float v00 = __shfl_sync(0xffffffffu, sacc[kc][0], s0l);
            float v01 = __shfl_sync(0xffffffffu, sacc[kc][1], s0l);
            float v10 = __shfl_sync(0xffffffffu, sacc[kc][2], s0l);
            float v11 = __shfl_sync(0xffffffffu, sacc[kc][3], s0l);
            float v20 = __shfl_sync(0xffffffffu, sacc[kc][0], s0l + 2);
            float v21 = __shfl_sync(0xffffffffu, sacc[kc][1], s0l + 2);
            float v30 = __shfl_sync(0xffffffffu, sacc[kc][2], s0l + 2);
            float v31 = __shfl_sync(0xffffffffu, sacc[kc][3], s0l + 2);
            uint32_t pa[4];
            pa[0] = f2tf32(odd ? v01 : v00);
            pa[1] = f2tf32(odd ? v11 : v10);
            pa[2] = f2tf32(odd ? v21 : v20);
            pa[3] = f2tf32(odd ? v31 : v30);
            #pragma unroll
            for (int dn = 0; dn < 8; dn++) {
                uint32_t bv[2];
                int vb = (dn * 8 + gid) * QP + kc * 8 + tig;
                bv[0] = Vt[vb];
                bv[1] = Vt[vb + 4];
                mma_tf32(oacc[dn], pa, bv);
            }
        }
    }

    #pragma unroll
    for (int o = 1; o <= 2; o <<= 1) {
        l0 += __shfl_xor_sync(0xffffffffu, l0, o);
        l1 += __shfl_xor_sync(0xffffffffu, l1, o);
    }
    float inv0 = 1.f / l0, inv1 = 1.f / l1;
    const int row0 = b * SEQ + q0 + wr0 + gid;
    #pragma unroll
    for (int dn = 0; dn < 8; dn++) {
        int col = h * HS + dn * 8 + 2 * tig;
        *reinterpret_cast<float2*>(&out[(size_t)row0 * EMBED + col]) =
            make_float2(oacc[dn][0] * inv0, oacc[dn][1] * inv0);
        *reinterpret_cast<float2*>(&out[(size_t)(row0 + 8) * EMBED + col]) =
            make_float2(oacc[dn][2] * inv1, oacc[dn][3] * inv1);
    }
}

// ------------------------- launch ------------------------------------------
extern "C" void kernel_launch(void* const* d_in, const int* in_sizes, int n_in,
                              void* d_out, int out_size) {
    (void)in_sizes; (void)n_in; (void)out_size;
    const float* x     = (const float*)d_in[0];
    const float* Wq    = (const float*)d_in[1];
    const float* bq    = (const float*)d_in[2];
    const float* Wk    = (const float*)d_in[3];
    const float* bk    = (const float*)d_in[4];
    const float* Wv    = (const float*)d_in[5];
    const float* bv    = (const float*)d_in[6];
    const float* Wp    = (const float*)d_in[7];
    const float* bp    = (const float*)d_in[8];
    const float* W1    = (const float*)d_in[9];
    const float* b1    = (const float*)d_in[10];
    const float* W2    = (const float*)d_in[11];
    const float* b2    = (const float*)d_in[12];
    const float* ln1_g = (const float*)d_in[13];
    const float* ln1_b = (const float*)d_in[14];
    const float* ln2_g = (const float*)d_in[15];
    const float* ln2_b = (const float*)d_in[16];
    float* out = (float*)d_out;

    float *p_qkv, *p_attn, *p_ff, *p_bqkv;
    uint32_t *p_wqkv16, *p_wp16, *p_w116, *p_w216;
    float2* p_stats;
    cudaGetSymbolAddress((void**)&p_qkv,    g_qkv);
    cudaGetSymbolAddress((void**)&p_attn,   g_attn);
    cudaGetSymbolAddress((void**)&p_ff,     g_ff);
    cudaGetSymbolAddress((void**)&p_wqkv16, g_wqkv16);
    cudaGetSymbolAddress((void**)&p_wp16,   g_wp16);
    cudaGetSymbolAddress((void**)&p_w116,   g_w116);
    cudaGetSymbolAddress((void**)&p_w216,   g_w216);
    cudaGetSymbolAddress((void**)&p_bqkv,   g_bqkv);
    cudaGetSymbolAddress((void**)&p_stats,  g_stats);

    cudaFuncSetAttribute(attn_tc_kernel,
                         cudaFuncAttributeMaxDynamicSharedMemorySize,
                         SM_ATTN_BYTES);
    cudaFuncSetAttribute(gemm_f16<true,  false>,
                         cudaFuncAttributeMaxDynamicSharedMemorySize, SM_GEMM_BYTES);
    cudaFuncSetAttribute(gemm_f16<false, false>,
                         cudaFuncAttributeMaxDynamicSharedMemorySize, SM_GEMM_BYTES);
    cudaFuncSetAttribute(gemm_f16<true,  true>,
                         cudaFuncAttributeMaxDynamicSharedMemorySize, SM_GEMM_BYTES);

    // 1. pack weights to half2 word layout
    pack_qkv16_kernel<<<(KW * NQKV + 255) / 256, 256>>>(
        Wq, Wk, Wv, bq, bk, bv, p_wqkv16, p_bqkv);
    pack_w16_kernel<<<(KW * EMBED + 255) / 256, 256>>>(Wp, p_wp16);
    pack_w16_kernel<<<(KW * EMBED + 255) / 256, 256>>>(W1, p_w116);
    pack_w16_kernel<<<(KW * EMBED + 255) / 256, 256>>>(W2, p_w216);

    // 2. LN1 stats
    ln_stats_kernel<<<ROWS / 8, 256>>>(x, p_stats);

    // 3. QKV projection, fused LN1 (fp16 tensor cores)
    gemm_f16<true, false><<<dim3(NQKV / 128, ROWS / 128), 256, SM_GEMM_BYTES>>>(
        x, p_wqkv16, p_bqkv, nullptr, p_qkv, NQKV, p_stats, ln1_g, ln1_b);

    // 4. causal attention (tf32, unchanged)
    attn_tc_kernel<<<dim3(2, HEADS, BATCH), 256, SM_ATTN_BYTES>>>(
        p_qkv, p_attn);

    // 5. output projection + residual
    gemm_f16<false, false><<<dim3(EMBED / 128, ROWS / 128), 256, SM_GEMM_BYTES>>>(
        p_attn, p_wp16, bp, x, out, EMBED, nullptr, nullptr, nullptr);

    // 6. LN2 stats
    ln_stats_kernel<<<ROWS / 8, 256>>>(out, p_stats);

    // 7. FFN1, fused LN2 + relu
    gemm_f16<true, true><<<dim3(EMBED / 128, ROWS / 128), 256, SM_GEMM_BYTES>>>(
        out, p_w116, b1, nullptr, p_ff, EMBED, p_stats, ln2_g, ln2_b);

    // 8. FFN2 + residual
    gemm_f16<false, false><<<dim3(EMBED / 128, ROWS / 128), 256, SM_GEMM_BYTES>>>(
        p_ff, p_w216, b2, out, out, EMBED, nullptr, nullptr, nullptr);
}

// round 14
// speedup vs baseline: 3.3564x; 1.0005x over previous
#include <cuda_runtime.h>
#include <cuda_fp16.h>
#include <math.h>
#include <stdint.h>

#define EMBED 384
#define HEADS 6
#define HS    64
#define BATCH 64
#define SEQ   256
#define ROWS  (BATCH*SEQ)     // 16384
#define NQKV  (3*EMBED)       // 1152
#define KW    (EMBED/2)       // 192 k-words (half2)

// ------------------------- device scratch (no allocs allowed) ----------------
__device__ float    g_qkv   [ROWS*NQKV];
__device__ float    g_attn  [ROWS*EMBED];
__device__ float    g_ff    [ROWS*EMBED];
__device__ uint32_t g_wqkv16[KW*NQKV];    // half2 words, [k_word][n]
__device__ uint32_t g_wp16  [KW*EMBED];
__device__ uint32_t g_w116  [KW*EMBED];
__device__ uint32_t g_w216  [KW*EMBED];
__device__ float    g_bqkv  [NQKV];
__device__ float2   g_stats [ROWS];

// ------------------------- helpers ------------------------------------------
__device__ __forceinline__ uint32_t f2tf32(float x) {
    uint32_t r;
    asm("cvt.rna.tf32.f32 %0, %1;" : "=r"(r) : "f"(x));
    return r;
}

__device__ __forceinline__ uint32_t pack_half2(float a, float b) {
    __half2 h = __floats2half2_rn(a, b);
    return *reinterpret_cast<uint32_t*>(&h);
}

__device__ __forceinline__ void mma_tf32(float d[4], const uint32_t a[4],
                                         const uint32_t b[2]) {
    asm volatile(
        "mma.sync.aligned.m16n8k8.row.col.f32.tf32.tf32.f32 "
        "{%0,%1,%2,%3}, {%4,%5,%6,%7}, {%8,%9}, {%0,%1,%2,%3};\n"
        : "+f"(d[0]), "+f"(d[1]), "+f"(d[2]), "+f"(d[3])
        : "r"(a[0]), "r"(a[1]), "r"(a[2]), "r"(a[3]), "r"(b[0]), "r"(b[1]));
}

__device__ __forceinline__ void mma_f16(float d[4], const uint32_t a[4],
                                        const uint32_t b[2]) {
    asm volatile(
        "mma.sync.aligned.m16n8k16.row.col.f32.f16.f16.f32 "
        "{%0,%1,%2,%3}, {%4,%5,%6,%7}, {%8,%9}, {%0,%1,%2,%3};\n"
        : "+f"(d[0]), "+f"(d[1]), "+f"(d[2]), "+f"(d[3])
        : "r"(a[0]), "r"(a[1]), "r"(a[2]), "r"(a[3]), "r"(b[0]), "r"(b[1]));
}

__device__ __forceinline__ void cp_async16(uint32_t saddr, const void* g) {
    asm volatile("cp.async.cg.shared.global [%0], [%1], 16;"
                 :: "r"(saddr), "l"(g));
}
#define CP_COMMIT() asm volatile("cp.async.commit_group;")
#define CP_WAIT0()  asm volatile("cp.async.wait_group 0;")

__device__ __forceinline__ uint32_t smem_u32(const void* p) {
    return (uint32_t)__cvta_generic_to_shared(p);
}

// ------------------------- weight packing (half2 word layout) ---------------
__global__ void pack_qkv16_kernel(const float* __restrict__ Wq,
                                  const float* __restrict__ Wk,
                                  const float* __restrict__ Wv,
                                  const float* __restrict__ bq,
                                  const float* __restrict__ bk,
                                  const float* __restrict__ bv,
                                  uint32_t* __restrict__ Wt,
                                  float* __restrict__ bout) {
    int idx = blockIdx.x * 256 + threadIdx.x;
    if (idx < KW * NQKV) {
        int w   = idx / NQKV;        // k-word (c pair)
        int n   = idx % NQKV;
        int sel = n / EMBED;
        int hd  = n % EMBED;
        int h   = hd / HS;
        int d   = hd % HS;
        const float* W = (sel == 0) ? Wq : (sel == 1) ? Wk : Wv;
        float v0 = W[((size_t)h * EMBED + 2 * w)     * HS + d];
        float v1 = W[((size_t)h * EMBED + 2 * w + 1) * HS + d];
        Wt[idx] = pack_half2(v0, v1);
    }
    if (idx < NQKV) {
        int sel = idx / EMBED;
        int hd  = idx % EMBED;
        const float* bb = (sel == 0) ? bq : (sel == 1) ? bk : bv;
        bout[idx] = bb[hd];
    }
}

__global__ void pack_w16_kernel(const float* __restrict__ W,
                                uint32_t* __restrict__ Wt) {
    int idx = blockIdx.x * 256 + threadIdx.x;
    if (idx < KW * EMBED) {
        int w = idx / EMBED;
        int n = idx % EMBED;
        Wt[idx] = pack_half2(W[(size_t)(2 * w) * EMBED + n],
                             W[(size_t)(2 * w + 1) * EMBED + n]);
    }
}

// ------------------------- LN stats ------------------------------------------
__global__ __launch_bounds__(256)
void ln_stats_kernel(const float* __restrict__ x, float2* __restrict__ st) {
    int row  = blockIdx.x * 8 + (threadIdx.x >> 5);
    int lane = threadIdx.x & 31;
    const float4* xr = reinterpret_cast<const float4*>(x + (size_t)row * EMBED);
    float s = 0.f, s2 = 0.f;
    #pragma unroll
    for (int i = 0; i < 3; i++) {
        float4 v = xr[lane + 32 * i];
        s  += v.x + v.y + v.z + v.w;
        s2 += v.x * v.x + v.y * v.y + v.z * v.z + v.w * v.w;
    }
    #pragma unroll
    for (int o = 16; o; o >>= 1) {
        s  += __shfl_xor_sync(0xffffffffu, s,  o);
        s2 += __shfl_xor_sync(0xffffffffu, s2, o);
    }
    if (lane == 0) {
        float mu  = s * (1.0f / EMBED);
        float var = s2 * (1.0f / EMBED) - mu * mu;
        st[row] = make_float2(mu, rsqrtf(var + 1e-5f));
    }
}

// ------------------------- FP16 tensor-core GEMM ----------------------------
// C[M,N] = A'[M,384] @ B[384,N] (+bias, opt relu, opt residual)
// A' = LN ? layernorm(A) : A (f32 in gmem, converted RN to half on STS).
// B pre-packed half2 words [k_word][n].  CTA 128x128, k-tile 64 (=32 words),
// 6 k-tiles, double-buffered, one sync per tile. mma m16n8k16 f16, f32 accum.
#define A_PITCH 36     // words; frag addr mod 32 = 4*gid + tig -> conflict-free
#define B_PITCH 136    // words; 136 mod 32 = 8 -> 8*tig + gid -> conflict-free
#define AS_WORDS (128 * A_PITCH)                 // 4608
#define BS_WORDS (32 * B_PITCH)                  // 4352
#define STG_WORDS (AS_WORDS + BS_WORDS)          // 8960
#define SM_GEMM_BYTES (2 * STG_WORDS * 4)        // 71680

template<bool LN, bool RELU>
__global__ __launch_bounds__(256)
void gemm_f16(const float* __restrict__ A, const uint32_t* __restrict__ Bw,
              const float* __restrict__ bias, const float* __restrict__ res,
              float* __restrict__ C, int N,
              const float2* __restrict__ stats,
              const float* __restrict__ lng, const float* __restrict__ lnb) {
    extern __shared__ uint32_t gsh[];
    const uint32_t smb = smem_u32(gsh);

    const int tid  = threadIdx.x;
    const int bm   = blockIdx.y * 128;
    const int bn   = blockIdx.x * 128;
    const int warp = tid >> 5;
    const int lane = tid & 31;
    const int wm   = (warp >> 2) * 64;
    const int wn   = (warp & 3) * 32;
    const int gid  = lane >> 2;
    const int tig  = lane & 3;

    float acc[4][4][4];
    #pragma unroll
    for (int i = 0; i < 4; i++)
        #pragma unroll
        for (int j = 0; j < 4; j++)
            #pragma unroll
            for (int r = 0; r < 4; r++) acc[i][j][r] = 0.f;

    // A staging: 8 chunks of float4 -> 2 half2 words each
    uint2 aS[8];
    const int a_row = tid >> 4;          // 0..15 (+16*it)
    const int a_f4  = tid & 15;          // float4 index within 64-float row

    auto ldgA = [&](int kt) {
        const int k0 = kt * 64;
        float4 gv, bv4;
        if (LN) {
            gv  = *reinterpret_cast<const float4*>(&lng[k0 + a_f4 * 4]);
            bv4 = *reinterpret_cast<const float4*>(&lnb[k0 + a_f4 * 4]);
        }
        #pragma unroll
        for (int it = 0; it < 8; it++) {
            int r = a_row + it * 16;
            float4 v = *reinterpret_cast<const float4*>(
                &A[(size_t)(bm + r) * EMBED + k0 + a_f4 * 4]);
            if (LN) {
                float2 st = stats[bm + r];
                v.x = fmaf((v.x - st.x) * st.y, gv.x, bv4.x);
                v.y = fmaf((v.y - st.x) * st.y, gv.y, bv4.y);
                v.z = fmaf((v.z - st.x) * st.y, gv.z, bv4.z);
                v.w = fmaf((v.w - st.x) * st.y, gv.w, bv4.w);
            }
            aS[it].x = pack_half2(v.x, v.y);
            aS[it].y = pack_half2(v.z, v.w);
        }
    };
    auto stsA = [&](int s) {
        uint32_t* As = gsh + s * STG_WORDS;
        #pragma unroll
        for (int it = 0; it < 8; it++) {
            int r = a_row + it * 16;
            As[r * A_PITCH + a_f4 * 2]     = aS[it].x;
            As[r * A_PITCH + a_f4 * 2 + 1] = aS[it].y;
        }
    };
    const int b_kr = tid >> 5;           // 0..7 (+8*it)
    const int b_n4 = (tid & 31) * 4;
    auto cpB = [&](int kt, int s) {
        const int k0w = kt * 32;
        const uint32_t b_sm = smb + (s * STG_WORDS + AS_WORDS) * 4;
        #pragma unroll
        for (int it = 0; it < 4; it++) {
            int kr = b_kr + it * 8;
            cp_async16(b_sm + (uint32_t)(kr * B_PITCH + b_n4) * 4,
                       &Bw[(size_t)(k0w + kr) * N + bn + b_n4]);
        }
        CP_COMMIT();
    };

    const int NT = 6;
    cpB(0, 0);
    ldgA(0);
    stsA(0);
    ldgA(1);
    CP_WAIT0();
    __syncthreads();

    for (int kt = 0; kt < NT; kt++) {
        const int cur = kt & 1;
        uint32_t* Asc = gsh + cur * STG_WORDS;
        uint32_t* Bsc = Asc + AS_WORDS;

        if (kt + 1 < NT) {               // stage kt+1 into cur^1
            stsA(cur ^ 1);
            cpB(kt + 1, cur ^ 1);
        }
        if (kt + 2 < NT) ldgA(kt + 2);

        #pragma unroll
        for (int ks = 0; ks < 4; ks++) {
            uint32_t af[4][4];
            #pragma unroll
            for (int mi = 0; mi < 4; mi++) {
                int row  = wm + mi * 16 + gid;
                int base = row * A_PITCH + ks * 8 + tig;
                af[mi][0] = Asc[base];
                af[mi][2] = Asc[base + 4];
                af[mi][1] = Asc[base + 8 * A_PITCH];
                af[mi][3] = Asc[base + 8 * A_PITCH + 4];
            }
            uint32_t bf[4][2];
            #pragma unroll
            for (int nj = 0; nj < 4; nj++) {
                int col = wn + nj * 8 + gid;
                bf[nj][0] = Bsc[(ks * 8 + tig)     * B_PITCH + col];
                bf[nj][1] = Bsc[(ks * 8 + tig + 4) * B_PITCH + col];
            }
            #pragma unroll
            for (int mi = 0; mi < 4; mi++)
                #pragma unroll
                for (int nj = 0; nj < 4; nj++)
                    mma_f16(acc[mi][nj], af[mi], bf[nj]);
        }
        CP_WAIT0();
        __syncthreads();
    }

    // epilogue (c-frag layout of m16n8k16 == m16n8k8)
    #pragma unroll
    for (int mi = 0; mi < 4; mi++) {
        int row = bm + wm + mi * 16 + gid;
        #pragma unroll
        for (int nj = 0; nj < 4; nj++) {
            int col = bn + wn + nj * 8 + tig * 2;
            float2 bv = *reinterpret_cast<const float2*>(&bias[col]);
            float v0 = acc[mi][nj][0] + bv.x;
            float v1 = acc[mi][nj][1] + bv.y;
            float v2 = acc[mi][nj][2] + bv.x;
            float v3 = acc[mi][nj][3] + bv.y;
            if (RELU) {
                v0 = fmaxf(v0, 0.f); v1 = fmaxf(v1, 0.f);
                v2 = fmaxf(v2, 0.f); v3 = fmaxf(v3, 0.f);
            }
            if (res) {
                float2 r0 = *reinterpret_cast<const float2*>(
                    &res[(size_t)row * N + col]);
                float2 r1 = *reinterpret_cast<const float2*>(
                    &res[(size_t)(row + 8) * N + col]);
                v0 += r0.x; v1 += r0.y; v2 += r1.x; v3 += r1.y;
            }
            *reinterpret_cast<float2*>(&C[(size_t)row * N + col]) =
                make_float2(v0, v1);
            *reinterpret_cast<float2*>(&C[(size_t)(row + 8) * N + col]) =
                make_float2(v2, v3);
        }
    }
}

// ------------------------- tensor-core flash attention (unchanged R10) ------
#define QP 68
#define SM_ATTN_BYTES ((128*QP + 2*64*QP + 2*64*QP) * 4)   // 104448

__global__ __launch_bounds__(256)
void attn_tc_kernel(const float* __restrict__ qkv, float* __restrict__ out) {
    extern __shared__ uint32_t sh[];
    uint32_t* Qs  = sh;
    uint32_t* Kb0 = sh + 128 * QP;
    uint32_t* Vb0 = sh + 128 * QP + 2 * 64 * QP;

    const int qt  = 1 - blockIdx.x;
    const int h   = blockIdx.y;
    const int b   = blockIdx.z;
    const int q0  = qt * 128;
    const int tid  = threadIdx.x;
    const int warp = tid >> 5;
    const int lane = tid & 31;
    const int gid  = lane >> 2;
    const int tig  = lane & 3;
    const int wr0  = warp * 16;
    const float qscale = rsqrtf((float)EMBED) * 1.4426950408889634f;

    #pragma unroll
    for (int it = 0; it < 8; it++) {
        int li = tid + it * 256;
        int r  = li >> 4;
        int d4 = (li & 15) * 4;
        float4 v = *reinterpret_cast<const float4*>(
            &qkv[(size_t)(b * SEQ + q0 + r) * NQKV + h * HS + d4]);
        uint4 u;
        u.x = f2tf32(v.x * qscale); u.y = f2tf32(v.y * qscale);
        u.z = f2tf32(v.z * qscale); u.w = f2tf32(v.w * qscale);
        *reinterpret_cast<uint4*>(&Qs[r * QP + d4]) = u;
    }

    const uint32_t kb_addr = smem_u32(Kb0);
    auto cpk = [&](int st, int stage) {
        const float* base = &qkv[(size_t)(b * SEQ + st * 64) * NQKV + EMBED + h * HS];
        uint32_t dst = kb_addr + (uint32_t)(stage * 64 * QP) * 4u;
        #pragma unroll
        for (int it = 0; it < 4; it++) {
            int cid = tid + it * 256;
            int r   = cid >> 4;
            int d4  = (cid & 15) * 4;
            cp_async16(dst + (uint32_t)(r * QP + d4) * 4u,
                       base + (size_t)r * NQKV + d4);
        }
        CP_COMMIT();
    };
    float4 vS[4];
    auto ldgv = [&](int st) {
        #pragma unroll
        for (int it = 0; it < 4; it++) {
            int li = tid + it * 256;
            int s  = li & 63;
            int d4 = (li >> 6) * 4;
            vS[it] = *reinterpret_cast<const float4*>(
                &qkv[(size_t)(b * SEQ + st * 64 + s) * NQKV + 2 * EMBED + h * HS + d4]);
        }
    };
    auto stsv = [&](uint32_t* Vt) {
        #pragma unroll
        for (int it = 0; it < 4; it++) {
            int li = tid + it * 256;
            int s  = li & 63;
            int d4 = (li >> 6) * 4;
            Vt[(d4 + 0) * QP + s] = f2tf32(vS[it].x);
            Vt[(d4 + 1) * QP + s] = f2tf32(vS[it].y);
            Vt[(d4 + 2) * QP + s] = f2tf32(vS[it].z);
            Vt[(d4 + 3) * QP + s] = f2tf32(vS[it].w);
        }
    };

    float oacc[8][4];
    #pragma unroll
    for (int i = 0; i < 8; i++)
        #pragma unroll
        for (int j = 0; j < 4; j++) oacc[i][j] = 0.f;
    float m0 = -1e30f, m1 = -1e30f, l0 = 0.f, l1 = 0.f;

    const int nst = q0 / 64 + 2;
    cpk(0, 0);
    ldgv(0);

    for (int st = 0; st < nst; st++) {
        const int cur = st & 1;
        uint32_t* Ks = Kb0 + cur * 64 * QP;
        uint32_t* Vt = Vb0 + cur * 64 * QP;

        __syncthreads();
        stsv(Vt);
        CP_WAIT0();
        __syncthreads();
        if (st + 1 < nst) {
            cpk(st + 1, cur ^ 1);
            ldgv(st + 1);
        }

        float sacc[8][4];
        #pragma unroll
        for (int i = 0; i < 8; i++)
            #pragma unroll
            for (int j = 0; j < 4; j++) sacc[i][j] = 0.f;

        #pragma unroll
        for (int ks = 0; ks < 8; ks++) {
            uint32_t qa[4];
            int qb = (wr0 + gid) * QP + ks * 8 + tig;
            qa[0] = Qs[qb];
            qa[1] = Qs[qb + 8 * QP];
            qa[2] = Qs[qb + 4];
            qa[3] = Qs[qb + 8 * QP + 4];
            #pragma unroll
            for (int nt = 0; nt < 8; nt++) {
                uint32_t bk[2];
                int kb = (nt * 8 + gid) * QP + ks * 8 + tig;
                bk[0] = Ks[kb];
                bk[1] = Ks[kb + 4];
                mma_tf32(sacc[nt], qa, bk);
            }
        }

        const int r0g = q0 + wr0 + gid;
        const int r1g = r0g + 8;
        if (st * 64 + 63 > r0g - gid) {
            #pragma unroll
            for (int nt = 0; nt < 8; nt++) {
                int cb = st * 64 + nt * 8 + 2 * tig;
                if (cb     > r0g) sacc[nt][0] = -1e30f;
                if (cb + 1 > r0g) sacc[nt][1] = -1e30f;
                if (cb     > r1g) sacc[nt][2] = -1e30f;
                if (cb + 1 > r1g) sacc[nt][3] = -1e30f;
            }
        }

        float mx0 = -1e30f, mx1 = -1e30f;
        #pragma unroll
        for (int nt = 0; nt < 8; nt++) {
            mx0 = fmaxf(mx0, fmaxf(sacc[nt][0], sacc[nt][1]));
            mx1 = fmaxf(mx1, fmaxf(sacc[nt][2], sacc[nt][3]));
        }
        #pragma unroll
        for (int o = 1; o <= 2; o <<= 1) {
            mx0 = fmaxf(mx0, __shfl_xor_sync(0xffffffffu, mx0, o));
            mx1 = fmaxf(mx1, __shfl_xor_sync(0xffffffffu, mx1, o));
        }
        float mn0 = fmaxf(m0, mx0), mn1 = fmaxf(m1, mx1);
        float al0 = exp2f(m0 - mn0), al1 = exp2f(m1 - mn1);
        m0 = mn0; m1 = mn1;

        float ls0 = 0.f, ls1 = 0.f;
        #pragma unroll
        for (int nt = 0; nt < 8; nt++) {
            float p0 = exp2f(sacc[nt][0] - mn0);
            float p1 = exp2f(sacc[nt][1] - mn0);
            float p2 = exp2f(sacc[nt][2] - mn1);
            float p3 = exp2f(sacc[nt][3] - mn1);
            sacc[nt][0] = p0; sacc[nt][1] = p1;
            sacc[nt][2] = p2; sacc[nt][3] = p3;
            ls0 += p0 + p1; ls1 += p2 + p3;
        }
        l0 = l0 * al0 + ls0;
        l1 = l1 * al1 + ls1;
        #pragma unroll
        for (int dn = 0; dn < 8; dn++) {
            oacc[dn][0] *= al0; oacc[dn][1] *= al0;
            oacc[dn][2] *= al1; oacc[dn][3] *= al1;
        }

        const int s0l = 4 * gid + (tig >> 1);
        const bool odd = tig & 1;
        #pragma unroll
        for (int kc = 0; kc < 8; kc++) {
            float v00 = __shfl_sync(0xffffffffu, sacc[kc][0], s0l);
            float v01 = __shfl_sync(0xffffffffu, sacc[kc][1], s0l);
            float v10 = __shfl_sync(0xffffffffu, sacc[kc][2], s0l);
            float v11 = __shfl_sync(0xffffffffu, sacc[kc][3], s0l);
            float v20 = __shfl_sync(0xffffffffu, sacc[kc][0], s0l + 2);
            float v21 = __shfl_sync(0xffffffffu, sacc[kc][1], s0l + 2);
            float v30 = __shfl_sync(0xffffffffu, sacc[kc][2], s0l + 2);
            float v31 = __shfl_sync(0xffffffffu, sacc[kc][3], s0l + 2);
            uint32_t pa[4];
            pa[0] = f2tf32(odd ? v01 : v00);
            pa[1] = f2tf32(odd ? v11 : v10);
            pa[2] = f2tf32(odd ? v21 : v20);
            pa[3] = f2tf32(odd ? v31 : v30);
            #pragma unroll
            for (int dn = 0; dn < 8; dn++) {
                uint32_t bv[2];
                int vb = (dn * 8 + gid) * QP + kc * 8 + tig;
                bv[0] = Vt[vb];
                bv[1] = Vt[vb + 4];
                mma_tf32(oacc[dn], pa, bv);
            }
        }
    }

    #pragma unroll
    for (int o = 1; o <= 2; o <<= 1) {
        l0 += __shfl_xor_sync(0xffffffffu, l0, o);
        l1 += __shfl_xor_sync(0xffffffffu, l1, o);
    }
    float inv0 = 1.f / l0, inv1 = 1.f / l1;
    const int row0 = b * SEQ + q0 + wr0 + gid;
    #pragma unroll
    for (int dn = 0; dn < 8; dn++) {
        int col = h * HS + dn * 8 + 2 * tig;
        *reinterpret_cast<float2*>(&out[(size_t)row0 * EMBED + col]) =
            make_float2(oacc[dn][0] * inv0, oacc[dn][1] * inv0);
        *reinterpret_cast<float2*>(&out[(size_t)(row0 + 8) * EMBED + col]) =
            make_float2(oacc[dn][2] * inv1, oacc[dn][3] * inv1);
    }
}

// ------------------------- launch ------------------------------------------
extern "C" void kernel_launch(void* const* d_in, const int* in_sizes, int n_in,
                              void* d_out, int out_size) {
    (void)in_sizes; (void)n_in; (void)out_size;
    const float* x     = (const float*)d_in[0];
    const float* Wq    = (const float*)d_in[1];
    const float* bq    = (const float*)d_in[2];
    const float* Wk    = (const float*)d_in[3];
    const float* bk    = (const float*)d_in[4];
    const float* Wv    = (const float*)d_in[5];
    const float* bv    = (const float*)d_in[6];
    const float* Wp    = (const float*)d_in[7];
    const float* bp    = (const float*)d_in[8];
    const float* W1    = (const float*)d_in[9];
    const float* b1    = (const float*)d_in[10];
    const float* W2    = (const float*)d_in[11];
    const float* b2    = (const float*)d_in[12];
    const float* ln1_g = (const float*)d_in[13];
    const float* ln1_b = (const float*)d_in[14];
    const float* ln2_g = (const float*)d_in[15];
    const float* ln2_b = (const float*)d_in[16];
    float* out = (float*)d_out;

    float *p_qkv, *p_attn, *p_ff, *p_bqkv;
    uint32_t *p_wqkv16, *p_wp16, *p_w116, *p_w216;
    float2* p_stats;
    cudaGetSymbolAddress((void**)&p_qkv,    g_qkv);
    cudaGetSymbolAddress((void**)&p_attn,   g_attn);
    cudaGetSymbolAddress((void**)&p_ff,     g_ff);
    cudaGetSymbolAddress((void**)&p_wqkv16, g_wqkv16);
    cudaGetSymbolAddress((void**)&p_wp16,   g_wp16);
    cudaGetSymbolAddress((void**)&p_w116,   g_w116);
    cudaGetSymbolAddress((void**)&p_w216,   g_w216);
    cudaGetSymbolAddress((void**)&p_bqkv,   g_bqkv);
    cudaGetSymbolAddress((void**)&p_stats,  g_stats);

    cudaFuncSetAttribute(attn_tc_kernel,
                         cudaFuncAttributeMaxDynamicSharedMemorySize,
                         SM_ATTN_BYTES);
    cudaFuncSetAttribute(gemm_f16<true,  false>,
                         cudaFuncAttributeMaxDynamicSharedMemorySize, SM_GEMM_BYTES);
    cudaFuncSetAttribute(gemm_f16<false, false>,
                         cudaFuncAttributeMaxDynamicSharedMemorySize, SM_GEMM_BYTES);
    cudaFuncSetAttribute(gemm_f16<true,  true>,
                         cudaFuncAttributeMaxDynamicSharedMemorySize, SM_GEMM_BYTES);

    // 1. pack weights to half2 word layout
    pack_qkv16_kernel<<<(KW * NQKV + 255) / 256, 256>>>(
        Wq, Wk, Wv, bq, bk, bv, p_wqkv16, p_bqkv);
    pack_w16_kernel<<<(KW * EMBED + 255) / 256, 256>>>(Wp, p_wp16);
    pack_w16_kernel<<<(KW * EMBED + 255) / 256, 256>>>(W1, p_w116);
    pack_w16_kernel<<<(KW * EMBED + 255) / 256, 256>>>(W2, p_w216);

    // 2. LN1 stats
    ln_stats_kernel<<<ROWS / 8, 256>>>(x, p_stats);

    // 3. QKV projection, fused LN1 (fp16 tensor cores)
    gemm_f16<true, false><<<dim3(NQKV / 128, ROWS / 128), 256, SM_GEMM_BYTES>>>(
        x, p_wqkv16, p_bqkv, nullptr, p_qkv, NQKV, p_stats, ln1_g, ln1_b);

    // 4. causal attention (tf32, unchanged)
    attn_tc_kernel<<<dim3(2, HEADS, BATCH), 256, SM_ATTN_BYTES>>>(
        p_qkv, p_attn);

    // 5. output projection + residual
    gemm_f16<false, false><<<dim3(EMBED / 128, ROWS / 128), 256, SM_GEMM_BYTES>>>(
        p_attn, p_wp16, bp, x, out, EMBED, nullptr, nullptr, nullptr);

    // 6. LN2 stats
    ln_stats_kernel<<<ROWS / 8, 256>>>(out, p_stats);

    // 7. FFN1, fused LN2 + relu
    gemm_f16<true, true><<<dim3(EMBED / 128, ROWS / 128), 256, SM_GEMM_BYTES>>>(
        out, p_w116, b1, nullptr, p_ff, EMBED, p_stats, ln2_g, ln2_b);

    // 8. FFN2 + residual
    gemm_f16<false, false><<<dim3(EMBED / 128, ROWS / 128), 256, SM_GEMM_BYTES>>>(
        p_ff, p_w216, b2, out, out, EMBED, nullptr, nullptr, nullptr);
}